// round 12
// baseline (speedup 1.0000x reference)
#include <cuda_runtime.h>
#include <cuda_fp16.h>
#include <cstdint>
#include <cstddef>

#define HID    1024
#define EMBED  512
#define BATCH  64
#define MAXLEN 1024
#define VOCAB  50257
#define NCHUNK 8
#define KSPL   4
#define AUXY   112        // (512 wout + 192 gh0 + 192 gh1) / NCHUNK

// ---------------- scratch (no allocations allowed) ----------------
__device__ float  g_dp4[KSPL * BATCH * HID];
__device__ float  g_epart[NCHUNK * MAXLEN * BATCH];
__device__ float  g_x[BATCH * (EMBED + HID)];
__device__ float  g_gi[KSPL * BATCH * 3 * HID];
__device__ float  g_gh0[KSPL * BATCH * 3 * HID];
__device__ float  g_gh1[KSPL * BATCH * 3 * HID];
__device__ float  g_h0[BATCH * HID];
__device__ __half g_bh[HID * HID];                     // w1e^T fp16 [n][k]
__device__ __half g_eh[(size_t)MAXLEN * BATCH * HID];  // enc fp16
__device__ __half g_wh[(size_t)VOCAB * HID];           // w_out fp16 [n][k]
__device__ __half g_h1h[BATCH * HID];                  // h1 fp16

// ---------------- shared K-split fp32 GEMM body (M=64, 256 threads) ----------------
template <bool BT>
__device__ __forceinline__ void gemm_body(const float* __restrict__ A,
                                          const float* __restrict__ B,
                                          float* __restrict__ C,
                                          int N, int K, int ldc, int nT, int ks) {
    __shared__ float As[64][16];
    __shared__ float Bs[16][64];
    const int Kseg = K / KSPL;
    A += ks * Kseg;                              // row stride stays K
    const float* Bp = BT ? (B + ks * Kseg) : (B + (size_t)ks * Kseg * N);
    C += (size_t)ks * 64 * ldc;
    const int tid = threadIdx.x;                 // callers guarantee tid < 256
    const int tx  = tid & 15, ty = tid >> 4;
    const int m4  = tid >> 2, kq = tid & 3;

    float acc[4][4] = {};
    for (int k0 = 0; k0 < Kseg; k0 += 16) {
        float4 avv = *(const float4*)(A + (size_t)m4 * K + k0 + kq * 4);
        *(float4*)&As[m4][kq * 4] = avv;
        if (BT) {
            int n = tid >> 2;
            int gn = nT + n;
            float4 bv = make_float4(0.f, 0.f, 0.f, 0.f);
            if (gn < N) bv = *(const float4*)(Bp + (size_t)gn * K + k0 + kq * 4);
            Bs[kq * 4 + 0][n] = bv.x;
            Bs[kq * 4 + 1][n] = bv.y;
            Bs[kq * 4 + 2][n] = bv.z;
            Bs[kq * 4 + 3][n] = bv.w;
        } else {
            #pragma unroll
            for (int e2 = 0; e2 < 4; e2++) {
                int lin = tid + e2 * 256;
                int kk = lin >> 6, n = lin & 63;
                int gn = nT + n;
                Bs[kk][n] = (gn < N) ? Bp[(size_t)(k0 + kk) * N + gn] : 0.f;
            }
        }
        __syncthreads();
        #pragma unroll
        for (int kk = 0; kk < 16; kk++) {
            float4 b4 = *(const float4*)&Bs[kk][tx * 4];
            float bj[4] = {b4.x, b4.y, b4.z, b4.w};
            #pragma unroll
            for (int i = 0; i < 4; i++) {
                float a = As[ty * 4 + i][kk];
                #pragma unroll
                for (int j = 0; j < 4; j++) acc[i][j] = fmaf(a, bj[j], acc[i][j]);
            }
        }
        __syncthreads();
    }
    #pragma unroll
    for (int i = 0; i < 4; i++) {
        int m = ty * 4 + i;
        #pragma unroll
        for (int j = 0; j < 4; j++) {
            int n = nT + tx * 4 + j;
            if (n < N) C[(size_t)m * ldc + n] = acc[i][j];
        }
    }
}

template <bool BT>
__global__ void gemm64_ks(const float* __restrict__ A, const float* __restrict__ B,
                          float* __restrict__ C, int N, int K, int ldc) {
    gemm_body<BT>(A, B, C, N, K, ldc, blockIdx.x * 64, blockIdx.y);
}

// ---------------- prep_all: enc->fp16 (main) + w1e transpose + dproj gemm (aux) ----------------
#define PREP_MAIN 65536                 // 64M elems / (256 thr * 4)
__global__ void prep_all(const float* __restrict__ enc,
                         const float* __restrict__ w1e,
                         const float* __restrict__ w1d,
                         const float* __restrict__ dec) {
    const int bid = blockIdx.x;
    const int tid = threadIdx.x;
    if (bid < PREP_MAIN) {
        size_t i = ((size_t)bid * 256 + tid) * 4;
        float4 v = *(const float4*)(enc + i);
        __half h[4];
        h[0] = __float2half_rn(v.x);
        h[1] = __float2half_rn(v.y);
        h[2] = __float2half_rn(v.z);
        h[3] = __float2half_rn(v.w);
        *(uint2*)(g_eh + i) = *(uint2*)h;
        return;
    }
    if (bid < PREP_MAIN + 1024) {       // w1e transpose+fp16
        __shared__ float tile[32][33];
        int pb = bid - PREP_MAIN;
        int k0 = (pb & 31) * 32, n0 = (pb >> 5) * 32;
        int tx = tid & 31, ty = tid >> 5;     // 32 x 8
        for (int i = ty; i < 32; i += 8)
            tile[i][tx] = w1e[(size_t)(k0 + i) * HID + n0 + tx];
        __syncthreads();
        for (int i = ty; i < 32; i += 8)
            g_bh[(size_t)(n0 + i) * HID + k0 + tx] = __float2half_rn(tile[tx][i]);
        return;
    }
    // dproj K-split gemm: 64 blocks
    int g = bid - (PREP_MAIN + 1024);
    gemm_body<false>(dec, w1d, g_dp4, HID, HID, HID, (g & 15) * 64, g >> 4);
}

// ---------------- helpers ----------------
__device__ __forceinline__ uint32_t smem_u32(const void* p) {
    uint32_t a;
    asm("{ .reg .u64 t; cvta.to.shared.u64 t, %1; cvt.u32.u64 %0, t; }" : "=r"(a) : "l"(p));
    return a;
}
__device__ __forceinline__ void cp16(void* s, const void* g) {
    asm volatile("cp.async.cg.shared.global [%0], [%1], 16;"
                 :: "r"(smem_u32(s)), "l"(g));
}
__device__ __forceinline__ void cp_commit() {
    asm volatile("cp.async.commit_group;" ::: "memory");
}
template <int N>
__device__ __forceinline__ void cp_wait() {
    asm volatile("cp.async.wait_group %0;" :: "n"(N) : "memory");
}
__device__ __forceinline__ void mma16816(float* d, const uint32_t* a, const uint32_t* b) {
    asm volatile("mma.sync.aligned.m16n8k16.row.col.f32.f16.f16.f32 "
                 "{%0,%1,%2,%3}, {%4,%5,%6,%7}, {%8,%9}, {%0,%1,%2,%3};"
                 : "+f"(d[0]), "+f"(d[1]), "+f"(d[2]), "+f"(d[3])
                 : "r"(a[0]), "r"(a[1]), "r"(a[2]), "r"(a[3]),
                   "r"(b[0]), "r"(b[1]));
}
__device__ __forceinline__ void ldsm4(uint32_t* r, uint32_t addr) {
    asm volatile("ldmatrix.sync.aligned.m8n8.x4.shared.b16 {%0,%1,%2,%3}, [%4];"
                 : "=r"(r[0]), "=r"(r[1]), "=r"(r[2]), "=r"(r[3]) : "r"(addr));
}

// ================= attention GEMM (+ aux: wout conversion, gh0/gh1 GEMMs) =================
#define ASTRIDE 72
#define MATH (128 * ASTRIDE)
#define STAGE_BYTES (2 * MATH * 2)
#define NSTAGE 4
#define SMEM_TOTAL_ATT (NSTAGE * STAGE_BYTES)
#define KC 64
#define KT (HID / KC)

__global__ void __launch_bounds__(512, 1)
attn_mma(const float* __restrict__ w2, const float* __restrict__ wout,
         const float* __restrict__ state, const float* __restrict__ dec,
         const float* __restrict__ whh0, const float* __restrict__ whh1) {
    extern __shared__ char smem[];
    const int tid = threadIdx.x;

    if (blockIdx.y >= 512) {
        const int aux = (blockIdx.y - 512) * NCHUNK + blockIdx.x;   // 0..895
        if (aux < 512) {
            // w_out fp32 -> fp16 (grid-stride)
            const size_t total4 = (size_t)VOCAB * HID / 4;
            for (size_t i = (size_t)aux * 512 + tid; i < total4; i += (size_t)512 * 512) {
                float4 v = *(const float4*)(wout + i * 4);
                __half h[4];
                h[0] = __float2half_rn(v.x);
                h[1] = __float2half_rn(v.y);
                h[2] = __float2half_rn(v.z);
                h[3] = __float2half_rn(v.w);
                *(uint2*)(g_wh + i * 4) = *(uint2*)h;
            }
            return;
        }
        if (tid >= 256) return;           // gemm body uses 256 threads
        const float* Ag; const float* Bg; float* Cg; int g;
        if (aux < 704) { g = aux - 512; Ag = state; Bg = whh0; Cg = g_gh0; }
        else           { g = aux - 704; Ag = dec;   Bg = whh1; Cg = g_gh1; }
        gemm_body<true>(Ag, Bg, Cg, 3 * HID, HID, 3 * HID, (g % 48) * 64, g / 48);
        return;
    }

    const uint32_t sbase = smem_u32(smem);
    const int bn = blockIdx.x;
    const int mt = blockIdx.y;
    const int wid = tid >> 5, lane = tid & 31;
    const int wm = wid >> 2, wn = wid & 3;
    const int qr = lane >> 2, qc = lane & 3;

    const __half* gAh = g_eh + (size_t)mt * 128 * HID;
    const __half* gBh = g_bh + (size_t)(bn * 128) * HID;

    const int lr = tid >> 2, lc = tid & 3;

    auto issue_load = [&](int kt) {
        char* base = smem + (kt % NSTAGE) * STAGE_BYTES;
        __half* sAh = (__half*)base;
        __half* sBh = sAh + MATH;
        #pragma unroll
        for (int i = 0; i < 2; i++) {
            int c = lc + i * 4;
            size_t go = (size_t)lr * HID + kt * KC + c * 8;
            int so = lr * ASTRIDE + c * 8;
            cp16(sAh + so, gAh + go);
            cp16(sBh + so, gBh + go);
        }
        cp_commit();
    };

    int offA[2];
    #pragma unroll
    for (int m = 0; m < 2; m++)
        offA[m] = ((wm * 32 + m * 16 + (lane & 15)) * ASTRIDE + (lane >> 4) * 8) * 2;
    int offB[2];
    #pragma unroll
    for (int j = 0; j < 2; j++)
        offB[j] = ((wn * 32 + (2 * j + (lane >> 4)) * 8 + (lane & 7)) * ASTRIDE
                   + ((lane >> 3) & 1) * 8) * 2;

    float acc[2][4][4] = {};

    auto compute = [&](int kt) {
        const uint32_t base = sbase + (kt % NSTAGE) * STAGE_BYTES;
        const uint32_t uAh = base;
        const uint32_t uBh = base + MATH * 2;
        #pragma unroll
        for (int ks = 0; ks < KC; ks += 16) {
            uint32_t ah[2][4], bh[4][2];
            #pragma unroll
            for (int m = 0; m < 2; m++)
                ldsm4(ah[m], uAh + offA[m] + ks * 2);
            #pragma unroll
            for (int j = 0; j < 2; j++) {
                uint32_t r[4];
                ldsm4(r, uBh + offB[j] + ks * 2);
                bh[2 * j][0] = r[0]; bh[2 * j][1] = r[1];
                bh[2 * j + 1][0] = r[2]; bh[2 * j + 1][1] = r[3];
            }
            #pragma unroll
            for (int m = 0; m < 2; m++)
                #pragma unroll
                for (int n = 0; n < 4; n++) mma16816(acc[m][n], ah[m], bh[n]);
        }
    };

    issue_load(0);
    issue_load(1);
    issue_load(2);
    for (int kt = 0; kt < KT; kt++) {
        cp_wait<2>();
        __syncthreads();
        if (kt + 3 < KT) issue_load(kt + 3);
        else cp_commit();
        compute(kt);
    }

    // epilogue: e_partial[row] = sum_n tanh(acc + sum_p dp4 + ...) * w2[n]
    float rsum[2][2] = {};
    #pragma unroll
    for (int m = 0; m < 2; m++) {
        #pragma unroll
        for (int n = 0; n < 4; n++) {
            int ng0 = bn * 128 + wn * 32 + n * 8 + qc * 2;
            float w20 = w2[ng0], w21 = w2[ng0 + 1];
            #pragma unroll
            for (int pr = 0; pr < 2; pr++) {
                int row_local = wm * 32 + m * 16 + qr + pr * 8;
                int b = row_local & 63;
                float d0 = 0.f, d1 = 0.f;
                #pragma unroll
                for (int p = 0; p < KSPL; p++) {
                    const float* dp = g_dp4 + p * (BATCH * HID) + (size_t)b * HID + ng0;
                    d0 += dp[0];
                    d1 += dp[1];
                }
                rsum[m][pr] += tanhf(acc[m][n][pr * 2 + 0] + d0) * w20
                             + tanhf(acc[m][n][pr * 2 + 1] + d1) * w21;
            }
        }
    }
    #pragma unroll
    for (int m = 0; m < 2; m++)
        #pragma unroll
        for (int pr = 0; pr < 2; pr++) {
            float v = rsum[m][pr];
            v += __shfl_xor_sync(0xffffffffu, v, 1);
            v += __shfl_xor_sync(0xffffffffu, v, 2);
            rsum[m][pr] = v;
        }
    float* part = (float*)smem;
    __syncthreads();
    if (qc == 0) {
        #pragma unroll
        for (int m = 0; m < 2; m++)
            #pragma unroll
            for (int pr = 0; pr < 2; pr++)
                part[(wm * 32 + m * 16 + qr + pr * 8) * 4 + wn] = rsum[m][pr];
    }
    __syncthreads();
    if (tid < 128) {
        float e = part[tid * 4 + 0] + part[tid * 4 + 1] + part[tid * 4 + 2] + part[tid * 4 + 3];
        g_epart[(size_t)bn * (MAXLEN * BATCH) + mt * 128 + tid] = e;
    }
}

// ================= fused softmax + context + build_x =================
__global__ void __launch_bounds__(1024, 1)
softmax_ctx(const int* __restrict__ cur, const float* __restrict__ emb) {
    const int b = blockIdx.x;           // one batch column per block
    const int tid = threadIdx.x;        // 1024 = one per t / one per h
    __shared__ float es[MAXLEN];
    __shared__ float red[1024];

    float s = 0.f;
    #pragma unroll
    for (int p = 0; p < NCHUNK; p++)
        s += g_epart[p * (MAXLEN * BATCH) + tid * 64 + b];
    red[tid] = s; __syncthreads();
    for (int st = 512; st; st >>= 1) {
        if (tid < st) red[tid] = fmaxf(red[tid], red[tid + st]);
        __syncthreads();
    }
    float mx = red[0]; __syncthreads();
    float v = __expf(s - mx);
    red[tid] = v; __syncthreads();
    for (int st = 512; st; st >>= 1) {
        if (tid < st) red[tid] += red[tid + st];
        __syncthreads();
    }
    float inv = 1.f / red[0];
    __syncthreads();
    es[tid] = v * inv;                  // alpha[t]
    __syncthreads();

    // context: h = tid
    float acc = 0.f;
    const __half* base = g_eh + (size_t)b * HID + tid;
    #pragma unroll 8
    for (int t = 0; t < MAXLEN; t++)
        acc = fmaf(es[t], __half2float(base[(size_t)t * 64 * HID]), acc);
    g_x[b * (EMBED + HID) + EMBED + tid] = acc;
    if (tid < EMBED)
        g_x[b * (EMBED + HID) + tid] = emb[(size_t)cur[b] * EMBED + tid];
}

// ================= logits GEMM: single-pass fp16 =================
#define L_ASTR 72
#define L_MA (64 * L_ASTR)
#define L_MB (128 * L_ASTR)
#define L_STAGE ((L_MA + L_MB) * 2)
#define L_NSTAGE 4
#define SMEM_TOTAL_LOG (L_NSTAGE * L_STAGE)

__global__ void __launch_bounds__(256, 1)
logits_mma(const float* __restrict__ bias, float* __restrict__ out) {
    extern __shared__ char smem[];
    const uint32_t sbase = smem_u32(smem);
    const int n0 = blockIdx.x * 128;
    const int tid = threadIdx.x;
    const int wid = tid >> 5, lane = tid & 31;
    const int wm = wid >> 2, wn = wid & 3;
    const int qr = lane >> 2, qc = lane & 3;

    const int ar = tid >> 2, ac = tid & 3;
    const int br = tid >> 1, bc0 = (tid & 1) * 4;

    auto issue_load = [&](int kt) {
        char* base = smem + (kt % L_NSTAGE) * L_STAGE;
        __half* sAh = (__half*)base;
        __half* sB  = sAh + L_MA;
        #pragma unroll
        for (int i = 0; i < 2; i++) {
            int c = ac + i * 4;
            size_t go = (size_t)ar * HID + kt * KC + c * 8;
            cp16(sAh + ar * L_ASTR + c * 8, g_h1h + go);
        }
        int gn = n0 + br; if (gn >= VOCAB) gn = VOCAB - 1;
        #pragma unroll
        for (int i = 0; i < 4; i++) {
            int c = bc0 + i;
            cp16(sB + br * L_ASTR + c * 8, g_wh + (size_t)gn * HID + kt * KC + c * 8);
        }
        cp_commit();
    };

    int offA[2];
    #pragma unroll
    for (int m = 0; m < 2; m++)
        offA[m] = ((wm * 32 + m * 16 + (lane & 15)) * L_ASTR + (lane >> 4) * 8) * 2;
    int offB[2];
    #pragma unroll
    for (int j = 0; j < 2; j++)
        offB[j] = ((wn * 32 + (2 * j + (lane >> 4)) * 8 + (lane & 7)) * L_ASTR
                   + ((lane >> 3) & 1) * 8) * 2;

    float acc[2][4][4] = {};

    auto compute = [&](int kt) {
        const uint32_t base = sbase + (kt % L_NSTAGE) * L_STAGE;
        const uint32_t uAh = base;
        const uint32_t uB  = base + L_MA * 2;
        #pragma unroll
        for (int ks = 0; ks < KC; ks += 16) {
            uint32_t ah[2][4], bb[4][2];
            #pragma unroll
            for (int m = 0; m < 2; m++)
                ldsm4(ah[m], uAh + offA[m] + ks * 2);
            #pragma unroll
            for (int j = 0; j < 2; j++) {
                uint32_t r[4];
                ldsm4(r, uB + offB[j] + ks * 2);
                bb[2 * j][0] = r[0]; bb[2 * j][1] = r[1];
                bb[2 * j + 1][0] = r[2]; bb[2 * j + 1][1] = r[3];
            }
            #pragma unroll
            for (int m = 0; m < 2; m++)
                #pragma unroll
                for (int n = 0; n < 4; n++) mma16816(acc[m][n], ah[m], bb[n]);
        }
    };

    issue_load(0);
    issue_load(1);
    issue_load(2);
    for (int kt = 0; kt < KT; kt++) {
        cp_wait<2>();
        __syncthreads();
        if (kt + 3 < KT) issue_load(kt + 3);
        else cp_commit();
        compute(kt);
    }

    #pragma unroll
    for (int m = 0; m < 2; m++) {
        #pragma unroll
        for (int n = 0; n < 4; n++) {
            int col = n0 + wn * 32 + n * 8 + qc * 2;
            #pragma unroll
            for (int pr = 0; pr < 2; pr++) {
                int row = wm * 32 + m * 16 + qr + pr * 8;
                if (col < VOCAB)
                    out[(size_t)row * VOCAB + col] = acc[m][n][pr * 2 + 0] + bias[col];
                if (col + 1 < VOCAB)
                    out[(size_t)row * VOCAB + col + 1] = acc[m][n][pr * 2 + 1] + bias[col + 1];
            }
        }
    }
}

// ---------------- GRU gates (reduces K-split partials; optional fp16 h out) ----------------
__global__ void gru_gates(const float* __restrict__ hprev,
                          const float* __restrict__ gh_part,
                          const float* __restrict__ b_ih,
                          const float* __restrict__ b_hh,
                          float* __restrict__ out1, float* __restrict__ out2,
                          int write_h1) {
    const int idx = blockIdx.x * 256 + threadIdx.x;
    const int b = idx >> 10, q = idx & 1023;
    const int base = b * 3072 + q;
    float ir = b_ih[q], iz = b_ih[q + 1024], in_ = b_ih[q + 2048];
    float hr = b_hh[q], hz = b_hh[q + 1024], hn = b_hh[q + 2048];
    #pragma unroll
    for (int p = 0; p < KSPL; p++) {
        const float* gi = g_gi + p * (BATCH * 3 * HID);
        const float* gh = gh_part + p * (BATCH * 3 * HID);
        ir += gi[base];        hr += gh[base];
        iz += gi[base + 1024]; hz += gh[base + 1024];
        in_ += gi[base + 2048]; hn += gh[base + 2048];
    }
    float r = 1.f / (1.f + __expf(-(ir + hr)));
    float z = 1.f / (1.f + __expf(-(iz + hz)));
    float n = tanhf(in_ + r * hn);
    float h = (1.f - z) * n + z * hprev[idx];
    out1[idx] = h;
    if (out2) out2[idx] = h;
    if (write_h1) g_h1h[idx] = __float2half_rn(h);
}

// ---------------- launch (single stream; graph-capture safe) ----------------
extern "C" void kernel_launch(void* const* d_in, const int* in_sizes, int n_in,
                              void* d_out, int out_size) {
    const int*   cur    = (const int*)d_in[0];
    const float* state  = (const float*)d_in[1];
    const float* enc    = (const float*)d_in[2];
    const float* emb    = (const float*)d_in[3];
    const float* w_att1 = (const float*)d_in[4];
    const float* w_att2 = (const float*)d_in[5];
    const float* w_ih0  = (const float*)d_in[6];
    const float* w_hh0  = (const float*)d_in[7];
    const float* b_ih0  = (const float*)d_in[8];
    const float* b_hh0  = (const float*)d_in[9];
    const float* w_ih1  = (const float*)d_in[10];
    const float* w_hh1  = (const float*)d_in[11];
    const float* b_ih1  = (const float*)d_in[12];
    const float* b_hh1  = (const float*)d_in[13];
    const float* w_out  = (const float*)d_in[14];
    const float* b_out  = (const float*)d_in[15];

    float* out = (float*)d_out;
    float* st0 = out + (size_t)BATCH * VOCAB;
    float* st1 = st0 + BATCH * HID;

    float *p_x, *p_gi, *p_gh0, *p_gh1, *p_h0;
    cudaGetSymbolAddress((void**)&p_x,   g_x);
    cudaGetSymbolAddress((void**)&p_gi,  g_gi);
    cudaGetSymbolAddress((void**)&p_gh0, g_gh0);
    cudaGetSymbolAddress((void**)&p_gh1, g_gh1);
    cudaGetSymbolAddress((void**)&p_h0,  g_h0);

    cudaFuncSetAttribute(attn_mma, cudaFuncAttributeMaxDynamicSharedMemorySize,
                         SMEM_TOTAL_ATT);
    cudaFuncSetAttribute(logits_mma, cudaFuncAttributeMaxDynamicSharedMemorySize,
                         SMEM_TOTAL_LOG);

    const float* dec = state + (size_t)BATCH * HID;

    // 1. prep_all: enc->fp16 + w1e transpose + dproj K-split gemm
    prep_all<<<PREP_MAIN + 1024 + 64, 256>>>(enc, w_att1,
                                             w_att1 + (size_t)HID * HID, dec);
    // 2. attention energies (+ aux: wout->fp16, gh0/gh1 GEMMs)
    attn_mma<<<dim3(NCHUNK, 512 + AUXY), 512, SMEM_TOTAL_ATT>>>(
        w_att2, w_out, state, dec, w_hh0, w_hh1);
    // 3. fused softmax + context + build_x
    softmax_ctx<<<BATCH, 1024>>>(cur, emb);
    // 4. GRU layer 0
    gemm64_ks<true><<<dim3(48, KSPL), 256>>>(p_x, w_ih0, p_gi, 3 * HID, EMBED + HID, 3 * HID);
    gru_gates<<<256, 256>>>(state, p_gh0, b_ih0, b_hh0, st0, p_h0, 0);
    // 5. GRU layer 1 (writes fp16 h1 for logits)
    gemm64_ks<true><<<dim3(48, KSPL), 256>>>(p_h0, w_ih1, p_gi, 3 * HID, HID, 3 * HID);
    gru_gates<<<256, 256>>>(dec, p_gh1, b_ih1, b_hh1, st1, nullptr, 1);
    // 6. logits
    logits_mma<<<(VOCAB + 127) / 128, 256, SMEM_TOTAL_LOG>>>(b_out, out);
}

// round 13
// speedup vs baseline: 1.0524x; 1.0524x over previous
#include <cuda_runtime.h>
#include <cuda_fp16.h>
#include <cstdint>
#include <cstddef>

#define HID    1024
#define EMBED  512
#define BATCH  64
#define MAXLEN 1024
#define VOCAB  50257
#define NCHUNK 8
#define KSPL   4
#define KSPLGI 8
#define AUXY   64          // 512 wout aux blocks / NCHUNK

// ---------------- scratch (no allocations allowed) ----------------
__device__ float  g_dp4[KSPL * BATCH * HID];
__device__ float  g_epart[NCHUNK * MAXLEN * BATCH];
__device__ float  g_x[BATCH * (EMBED + HID)];
__device__ float  g_gi[KSPLGI * BATCH * 3 * HID];
__device__ float  g_gh0[KSPL * BATCH * 3 * HID];
__device__ float  g_gh1[KSPL * BATCH * 3 * HID];
__device__ float  g_h0[BATCH * HID];
__device__ __half g_bh[HID * HID];                     // w1e^T fp16 [n][k]
__device__ __half g_eh[(size_t)MAXLEN * BATCH * HID];  // enc fp16
__device__ __half g_wh[(size_t)VOCAB * HID];           // w_out fp16 [n][k]
__device__ __half g_h1h[BATCH * HID];                  // h1 fp16

// ---------------- K-split fp32 GEMM body (M=64, 256 threads) ----------------
template <bool BT, int NS>
__device__ __forceinline__ void gemm_body(const float* __restrict__ A,
                                          const float* __restrict__ B,
                                          float* __restrict__ C,
                                          int N, int K, int ldc, int nT, int ks) {
    __shared__ float As[64][16];
    __shared__ float Bs[16][64];
    const int Kseg = K / NS;
    A += ks * Kseg;                              // row stride stays K
    const float* Bp = BT ? (B + ks * Kseg) : (B + (size_t)ks * Kseg * N);
    C += (size_t)ks * 64 * ldc;
    const int tid = threadIdx.x;                 // callers guarantee tid < 256
    const int tx  = tid & 15, ty = tid >> 4;
    const int m4  = tid >> 2, kq = tid & 3;

    float acc[4][4] = {};
    for (int k0 = 0; k0 < Kseg; k0 += 16) {
        float4 avv = *(const float4*)(A + (size_t)m4 * K + k0 + kq * 4);
        *(float4*)&As[m4][kq * 4] = avv;
        if (BT) {
            int n = tid >> 2;
            int gn = nT + n;
            float4 bv = make_float4(0.f, 0.f, 0.f, 0.f);
            if (gn < N) bv = *(const float4*)(Bp + (size_t)gn * K + k0 + kq * 4);
            Bs[kq * 4 + 0][n] = bv.x;
            Bs[kq * 4 + 1][n] = bv.y;
            Bs[kq * 4 + 2][n] = bv.z;
            Bs[kq * 4 + 3][n] = bv.w;
        } else {
            #pragma unroll
            for (int e2 = 0; e2 < 4; e2++) {
                int lin = tid + e2 * 256;
                int kk = lin >> 6, n = lin & 63;
                int gn = nT + n;
                Bs[kk][n] = (gn < N) ? Bp[(size_t)(k0 + kk) * N + gn] : 0.f;
            }
        }
        __syncthreads();
        #pragma unroll
        for (int kk = 0; kk < 16; kk++) {
            float4 b4 = *(const float4*)&Bs[kk][tx * 4];
            float bj[4] = {b4.x, b4.y, b4.z, b4.w};
            #pragma unroll
            for (int i = 0; i < 4; i++) {
                float a = As[ty * 4 + i][kk];
                #pragma unroll
                for (int j = 0; j < 4; j++) acc[i][j] = fmaf(a, bj[j], acc[i][j]);
            }
        }
        __syncthreads();
    }
    #pragma unroll
    for (int i = 0; i < 4; i++) {
        int m = ty * 4 + i;
        #pragma unroll
        for (int j = 0; j < 4; j++) {
            int n = nT + tx * 4 + j;
            if (n < N) C[(size_t)m * ldc + n] = acc[i][j];
        }
    }
}

template <bool BT, int NS>
__global__ void gemm64_ks(const float* __restrict__ A, const float* __restrict__ B,
                          float* __restrict__ C, int N, int K, int ldc) {
    gemm_body<BT, NS>(A, B, C, N, K, ldc, blockIdx.x * 64, blockIdx.y);
}

// ------- prep_all: enc->fp16 (main) + w1e transpose + dproj + gh0/gh1 GEMMs (aux) -------
#define PREP_MAIN 65536                 // 64M elems / (256 thr * 4)
__global__ void prep_all(const float* __restrict__ enc,
                         const float* __restrict__ w1e,
                         const float* __restrict__ w1d,
                         const float* __restrict__ state,
                         const float* __restrict__ dec,
                         const float* __restrict__ whh0,
                         const float* __restrict__ whh1) {
    const int bid = blockIdx.x;
    const int tid = threadIdx.x;
    if (bid < PREP_MAIN) {
        size_t i = ((size_t)bid * 256 + tid) * 4;
        float4 v = *(const float4*)(enc + i);
        __half h[4];
        h[0] = __float2half_rn(v.x);
        h[1] = __float2half_rn(v.y);
        h[2] = __float2half_rn(v.z);
        h[3] = __float2half_rn(v.w);
        *(uint2*)(g_eh + i) = *(uint2*)h;
        return;
    }
    int aux = bid - PREP_MAIN;
    if (aux < 1024) {                   // w1e transpose+fp16
        __shared__ float tile[32][33];
        int k0 = (aux & 31) * 32, n0 = (aux >> 5) * 32;
        int tx = tid & 31, ty = tid >> 5;     // 32 x 8
        for (int i = ty; i < 32; i += 8)
            tile[i][tx] = w1e[(size_t)(k0 + i) * HID + n0 + tx];
        __syncthreads();
        for (int i = ty; i < 32; i += 8)
            g_bh[(size_t)(n0 + i) * HID + k0 + tx] = __float2half_rn(tile[tx][i]);
        return;
    }
    aux -= 1024;
    if (aux < 64) {                     // dproj K-split gemm (16 x 4)
        gemm_body<false, KSPL>(dec, w1d, g_dp4, HID, HID, HID,
                               (aux & 15) * 64, aux >> 4);
        return;
    }
    aux -= 64;
    if (aux < 192) {                    // gh0 (48 x 4)
        gemm_body<true, KSPL>(state, whh0, g_gh0, 3 * HID, HID, 3 * HID,
                              (aux % 48) * 64, aux / 48);
        return;
    }
    aux -= 192;                         // gh1 (48 x 4)
    gemm_body<true, KSPL>(dec, whh1, g_gh1, 3 * HID, HID, 3 * HID,
                          (aux % 48) * 64, aux / 48);
}
#define PREP_BLOCKS (PREP_MAIN + 1024 + 64 + 192 + 192)

// ---------------- helpers ----------------
__device__ __forceinline__ uint32_t smem_u32(const void* p) {
    uint32_t a;
    asm("{ .reg .u64 t; cvta.to.shared.u64 t, %1; cvt.u32.u64 %0, t; }" : "=r"(a) : "l"(p));
    return a;
}
__device__ __forceinline__ void cp16(void* s, const void* g) {
    asm volatile("cp.async.cg.shared.global [%0], [%1], 16;"
                 :: "r"(smem_u32(s)), "l"(g));
}
__device__ __forceinline__ void cp_commit() {
    asm volatile("cp.async.commit_group;" ::: "memory");
}
template <int N>
__device__ __forceinline__ void cp_wait() {
    asm volatile("cp.async.wait_group %0;" :: "n"(N) : "memory");
}
__device__ __forceinline__ void mma16816(float* d, const uint32_t* a, const uint32_t* b) {
    asm volatile("mma.sync.aligned.m16n8k16.row.col.f32.f16.f16.f32 "
                 "{%0,%1,%2,%3}, {%4,%5,%6,%7}, {%8,%9}, {%0,%1,%2,%3};"
                 : "+f"(d[0]), "+f"(d[1]), "+f"(d[2]), "+f"(d[3])
                 : "r"(a[0]), "r"(a[1]), "r"(a[2]), "r"(a[3]),
                   "r"(b[0]), "r"(b[1]));
}
__device__ __forceinline__ void ldsm4(uint32_t* r, uint32_t addr) {
    asm volatile("ldmatrix.sync.aligned.m8n8.x4.shared.b16 {%0,%1,%2,%3}, [%4];"
                 : "=r"(r[0]), "=r"(r[1]), "=r"(r[2]), "=r"(r[3]) : "r"(addr));
}

// ================= attention GEMM (+ wout conversion aux only) =================
#define ASTRIDE 72
#define MATH (128 * ASTRIDE)
#define STAGE_BYTES (2 * MATH * 2)
#define NSTAGE 4
#define SMEM_TOTAL_ATT (NSTAGE * STAGE_BYTES)
#define KC 64
#define KT (HID / KC)

__global__ void __launch_bounds__(512, 1)
attn_mma(const float* __restrict__ w2, const float* __restrict__ wout) {
    extern __shared__ char smem[];
    const int tid = threadIdx.x;

    if (blockIdx.y >= 512) {
        const int aux = (blockIdx.y - 512) * NCHUNK + blockIdx.x;   // 0..511
        const size_t total4 = (size_t)VOCAB * HID / 4;
        for (size_t i = (size_t)aux * 512 + tid; i < total4; i += (size_t)512 * 512) {
            float4 v = *(const float4*)(wout + i * 4);
            __half h[4];
            h[0] = __float2half_rn(v.x);
            h[1] = __float2half_rn(v.y);
            h[2] = __float2half_rn(v.z);
            h[3] = __float2half_rn(v.w);
            *(uint2*)(g_wh + i * 4) = *(uint2*)h;
        }
        return;
    }

    const uint32_t sbase = smem_u32(smem);
    const int bn = blockIdx.x;
    const int mt = blockIdx.y;
    const int wid = tid >> 5, lane = tid & 31;
    const int wm = wid >> 2, wn = wid & 3;
    const int qr = lane >> 2, qc = lane & 3;

    const __half* gAh = g_eh + (size_t)mt * 128 * HID;
    const __half* gBh = g_bh + (size_t)(bn * 128) * HID;

    const int lr = tid >> 2, lc = tid & 3;

    auto issue_load = [&](int kt) {
        char* base = smem + (kt % NSTAGE) * STAGE_BYTES;
        __half* sAh = (__half*)base;
        __half* sBh = sAh + MATH;
        #pragma unroll
        for (int i = 0; i < 2; i++) {
            int c = lc + i * 4;
            size_t go = (size_t)lr * HID + kt * KC + c * 8;
            int so = lr * ASTRIDE + c * 8;
            cp16(sAh + so, gAh + go);
            cp16(sBh + so, gBh + go);
        }
        cp_commit();
    };

    int offA[2];
    #pragma unroll
    for (int m = 0; m < 2; m++)
        offA[m] = ((wm * 32 + m * 16 + (lane & 15)) * ASTRIDE + (lane >> 4) * 8) * 2;
    int offB[2];
    #pragma unroll
    for (int j = 0; j < 2; j++)
        offB[j] = ((wn * 32 + (2 * j + (lane >> 4)) * 8 + (lane & 7)) * ASTRIDE
                   + ((lane >> 3) & 1) * 8) * 2;

    float acc[2][4][4] = {};

    auto compute = [&](int kt) {
        const uint32_t base = sbase + (kt % NSTAGE) * STAGE_BYTES;
        const uint32_t uAh = base;
        const uint32_t uBh = base + MATH * 2;
        #pragma unroll
        for (int ks = 0; ks < KC; ks += 16) {
            uint32_t ah[2][4], bh[4][2];
            #pragma unroll
            for (int m = 0; m < 2; m++)
                ldsm4(ah[m], uAh + offA[m] + ks * 2);
            #pragma unroll
            for (int j = 0; j < 2; j++) {
                uint32_t r[4];
                ldsm4(r, uBh + offB[j] + ks * 2);
                bh[2 * j][0] = r[0]; bh[2 * j][1] = r[1];
                bh[2 * j + 1][0] = r[2]; bh[2 * j + 1][1] = r[3];
            }
            #pragma unroll
            for (int m = 0; m < 2; m++)
                #pragma unroll
                for (int n = 0; n < 4; n++) mma16816(acc[m][n], ah[m], bh[n]);
        }
    };

    issue_load(0);
    issue_load(1);
    issue_load(2);
    for (int kt = 0; kt < KT; kt++) {
        cp_wait<2>();
        __syncthreads();
        if (kt + 3 < KT) issue_load(kt + 3);
        else cp_commit();
        compute(kt);
    }

    // epilogue: e_partial = sum_n tanh(acc + sum_p dp4) * w2[n]
    float rsum[2][2] = {};
    #pragma unroll
    for (int m = 0; m < 2; m++) {
        #pragma unroll
        for (int n = 0; n < 4; n++) {
            int ng0 = bn * 128 + wn * 32 + n * 8 + qc * 2;
            float w20 = w2[ng0], w21 = w2[ng0 + 1];
            #pragma unroll
            for (int pr = 0; pr < 2; pr++) {
                int row_local = wm * 32 + m * 16 + qr + pr * 8;
                int b = row_local & 63;
                float d0 = 0.f, d1 = 0.f;
                #pragma unroll
                for (int p = 0; p < KSPL; p++) {
                    const float* dp = g_dp4 + p * (BATCH * HID) + (size_t)b * HID + ng0;
                    d0 += dp[0];
                    d1 += dp[1];
                }
                rsum[m][pr] += tanhf(acc[m][n][pr * 2 + 0] + d0) * w20
                             + tanhf(acc[m][n][pr * 2 + 1] + d1) * w21;
            }
        }
    }
    #pragma unroll
    for (int m = 0; m < 2; m++)
        #pragma unroll
        for (int pr = 0; pr < 2; pr++) {
            float v = rsum[m][pr];
            v += __shfl_xor_sync(0xffffffffu, v, 1);
            v += __shfl_xor_sync(0xffffffffu, v, 2);
            rsum[m][pr] = v;
        }
    float* part = (float*)smem;
    __syncthreads();
    if (qc == 0) {
        #pragma unroll
        for (int m = 0; m < 2; m++)
            #pragma unroll
            for (int pr = 0; pr < 2; pr++)
                part[(wm * 32 + m * 16 + qr + pr * 8) * 4 + wn] = rsum[m][pr];
    }
    __syncthreads();
    if (tid < 128) {
        float e = part[tid * 4 + 0] + part[tid * 4 + 1] + part[tid * 4 + 2] + part[tid * 4 + 3];
        g_epart[(size_t)bn * (MAXLEN * BATCH) + mt * 128 + tid] = e;
    }
}

// ================= fused softmax + context + build_x =================
__global__ void __launch_bounds__(1024, 1)
softmax_ctx(const int* __restrict__ cur, const float* __restrict__ emb) {
    const int b = blockIdx.x;
    const int tid = threadIdx.x;
    __shared__ float es[MAXLEN];
    __shared__ float red[1024];

    float s = 0.f;
    #pragma unroll
    for (int p = 0; p < NCHUNK; p++)
        s += g_epart[p * (MAXLEN * BATCH) + tid * 64 + b];
    red[tid] = s; __syncthreads();
    for (int st = 512; st; st >>= 1) {
        if (tid < st) red[tid] = fmaxf(red[tid], red[tid + st]);
        __syncthreads();
    }
    float mx = red[0]; __syncthreads();
    float v = __expf(s - mx);
    red[tid] = v; __syncthreads();
    for (int st = 512; st; st >>= 1) {
        if (tid < st) red[tid] += red[tid + st];
        __syncthreads();
    }
    float inv = 1.f / red[0];
    __syncthreads();
    es[tid] = v * inv;
    __syncthreads();

    float acc = 0.f;
    const __half* base = g_eh + (size_t)b * HID + tid;
    #pragma unroll 8
    for (int t = 0; t < MAXLEN; t++)
        acc = fmaf(es[t], __half2float(base[(size_t)t * 64 * HID]), acc);
    g_x[b * (EMBED + HID) + EMBED + tid] = acc;
    if (tid < EMBED)
        g_x[b * (EMBED + HID) + tid] = emb[(size_t)cur[b] * EMBED + tid];
}

// ================= logits GEMM: single-pass fp16 =================
#define L_ASTR 72
#define L_MA (64 * L_ASTR)
#define L_MB (128 * L_ASTR)
#define L_STAGE ((L_MA + L_MB) * 2)
#define L_NSTAGE 4
#define SMEM_TOTAL_LOG (L_NSTAGE * L_STAGE)

__global__ void __launch_bounds__(256, 1)
logits_mma(const float* __restrict__ bias, float* __restrict__ out) {
    extern __shared__ char smem[];
    const uint32_t sbase = smem_u32(smem);
    const int n0 = blockIdx.x * 128;
    const int tid = threadIdx.x;
    const int wid = tid >> 5, lane = tid & 31;
    const int wm = wid >> 2, wn = wid & 3;
    const int qr = lane >> 2, qc = lane & 3;

    const int ar = tid >> 2, ac = tid & 3;
    const int br = tid >> 1, bc0 = (tid & 1) * 4;

    auto issue_load = [&](int kt) {
        char* base = smem + (kt % L_NSTAGE) * L_STAGE;
        __half* sAh = (__half*)base;
        __half* sB  = sAh + L_MA;
        #pragma unroll
        for (int i = 0; i < 2; i++) {
            int c = ac + i * 4;
            size_t go = (size_t)ar * HID + kt * KC + c * 8;
            cp16(sAh + ar * L_ASTR + c * 8, g_h1h + go);
        }
        int gn = n0 + br; if (gn >= VOCAB) gn = VOCAB - 1;
        #pragma unroll
        for (int i = 0; i < 4; i++) {
            int c = bc0 + i;
            cp16(sB + br * L_ASTR + c * 8, g_wh + (size_t)gn * HID + kt * KC + c * 8);
        }
        cp_commit();
    };

    int offA[2];
    #pragma unroll
    for (int m = 0; m < 2; m++)
        offA[m] = ((wm * 32 + m * 16 + (lane & 15)) * L_ASTR + (lane >> 4) * 8) * 2;
    int offB[2];
    #pragma unroll
    for (int j = 0; j < 2; j++)
        offB[j] = ((wn * 32 + (2 * j + (lane >> 4)) * 8 + (lane & 7)) * L_ASTR
                   + ((lane >> 3) & 1) * 8) * 2;

    float acc[2][4][4] = {};

    auto compute = [&](int kt) {
        const uint32_t base = sbase + (kt % L_NSTAGE) * L_STAGE;
        const uint32_t uAh = base;
        const uint32_t uB  = base + L_MA * 2;
        #pragma unroll
        for (int ks = 0; ks < KC; ks += 16) {
            uint32_t ah[2][4], bb[4][2];
            #pragma unroll
            for (int m = 0; m < 2; m++)
                ldsm4(ah[m], uAh + offA[m] + ks * 2);
            #pragma unroll
            for (int j = 0; j < 2; j++) {
                uint32_t r[4];
                ldsm4(r, uB + offB[j] + ks * 2);
                bb[2 * j][0] = r[0]; bb[2 * j][1] = r[1];
                bb[2 * j + 1][0] = r[2]; bb[2 * j + 1][1] = r[3];
            }
            #pragma unroll
            for (int m = 0; m < 2; m++)
                #pragma unroll
                for (int n = 0; n < 4; n++) mma16816(acc[m][n], ah[m], bb[n]);
        }
    };

    issue_load(0);
    issue_load(1);
    issue_load(2);
    for (int kt = 0; kt < KT; kt++) {
        cp_wait<2>();
        __syncthreads();
        if (kt + 3 < KT) issue_load(kt + 3);
        else cp_commit();
        compute(kt);
    }

    #pragma unroll
    for (int m = 0; m < 2; m++) {
        #pragma unroll
        for (int n = 0; n < 4; n++) {
            int col = n0 + wn * 32 + n * 8 + qc * 2;
            #pragma unroll
            for (int pr = 0; pr < 2; pr++) {
                int row = wm * 32 + m * 16 + qr + pr * 8;
                if (col < VOCAB)
                    out[(size_t)row * VOCAB + col] = acc[m][n][pr * 2 + 0] + bias[col];
                if (col + 1 < VOCAB)
                    out[(size_t)row * VOCAB + col + 1] = acc[m][n][pr * 2 + 1] + bias[col + 1];
            }
        }
    }
}

// ---------------- GRU gates (reduces gi x8 + gh x4 partials; optional fp16 h1) ----------------
__global__ void gru_gates(const float* __restrict__ hprev,
                          const float* __restrict__ gh_part,
                          const float* __restrict__ b_ih,
                          const float* __restrict__ b_hh,
                          float* __restrict__ out1, float* __restrict__ out2,
                          int write_h1) {
    const int idx = blockIdx.x * 256 + threadIdx.x;
    const int b = idx >> 10, q = idx & 1023;
    const int base = b * 3072 + q;
    float ir = b_ih[q], iz = b_ih[q + 1024], in_ = b_ih[q + 2048];
    float hr = b_hh[q], hz = b_hh[q + 1024], hn = b_hh[q + 2048];
    #pragma unroll
    for (int p = 0; p < KSPLGI; p++) {
        const float* gi = g_gi + p * (BATCH * 3 * HID);
        ir  += gi[base];
        iz  += gi[base + 1024];
        in_ += gi[base + 2048];
    }
    #pragma unroll
    for (int p = 0; p < KSPL; p++) {
        const float* gh = gh_part + p * (BATCH * 3 * HID);
        hr += gh[base];
        hz += gh[base + 1024];
        hn += gh[base + 2048];
    }
    float r = 1.f / (1.f + __expf(-(ir + hr)));
    float z = 1.f / (1.f + __expf(-(iz + hz)));
    float n = tanhf(in_ + r * hn);
    float h = (1.f - z) * n + z * hprev[idx];
    out1[idx] = h;
    if (out2) out2[idx] = h;
    if (write_h1) g_h1h[idx] = __float2half_rn(h);
}

// ---------------- launch (single stream; graph-capture safe) ----------------
extern "C" void kernel_launch(void* const* d_in, const int* in_sizes, int n_in,
                              void* d_out, int out_size) {
    const int*   cur    = (const int*)d_in[0];
    const float* state  = (const float*)d_in[1];
    const float* enc    = (const float*)d_in[2];
    const float* emb    = (const float*)d_in[3];
    const float* w_att1 = (const float*)d_in[4];
    const float* w_att2 = (const float*)d_in[5];
    const float* w_ih0  = (const float*)d_in[6];
    const float* w_hh0  = (const float*)d_in[7];
    const float* b_ih0  = (const float*)d_in[8];
    const float* b_hh0  = (const float*)d_in[9];
    const float* w_ih1  = (const float*)d_in[10];
    const float* w_hh1  = (const float*)d_in[11];
    const float* b_ih1  = (const float*)d_in[12];
    const float* b_hh1  = (const float*)d_in[13];
    const float* w_out  = (const float*)d_in[14];
    const float* b_out  = (const float*)d_in[15];

    float* out = (float*)d_out;
    float* st0 = out + (size_t)BATCH * VOCAB;
    float* st1 = st0 + BATCH * HID;

    float *p_x, *p_gi, *p_gh0, *p_gh1, *p_h0;
    cudaGetSymbolAddress((void**)&p_x,   g_x);
    cudaGetSymbolAddress((void**)&p_gi,  g_gi);
    cudaGetSymbolAddress((void**)&p_gh0, g_gh0);
    cudaGetSymbolAddress((void**)&p_gh1, g_gh1);
    cudaGetSymbolAddress((void**)&p_h0,  g_h0);

    cudaFuncSetAttribute(attn_mma, cudaFuncAttributeMaxDynamicSharedMemorySize,
                         SMEM_TOTAL_ATT);
    cudaFuncSetAttribute(logits_mma, cudaFuncAttributeMaxDynamicSharedMemorySize,
                         SMEM_TOTAL_LOG);

    const float* dec = state + (size_t)BATCH * HID;

    // 1. prep_all: enc->fp16 + w1e transpose + dproj + gh0/gh1 GEMMs
    prep_all<<<PREP_BLOCKS, 256>>>(enc, w_att1, w_att1 + (size_t)HID * HID,
                                   state, dec, w_hh0, w_hh1);
    // 2. attention energies (+ wout->fp16 aux)
    attn_mma<<<dim3(NCHUNK, 512 + AUXY), 512, SMEM_TOTAL_ATT>>>(w_att2, w_out);
    // 3. fused softmax + context + build_x
    softmax_ctx<<<BATCH, 1024>>>(cur, emb);
    // 4. GRU layer 0 (gi K-split x8)
    gemm64_ks<true, KSPLGI><<<dim3(48, KSPLGI), 256>>>(p_x, w_ih0, p_gi,
                                                       3 * HID, EMBED + HID, 3 * HID);
    gru_gates<<<256, 256>>>(state, p_gh0, b_ih0, b_hh0, st0, p_h0, 0);
    // 5. GRU layer 1 (writes fp16 h1)
    gemm64_ks<true, KSPLGI><<<dim3(48, KSPLGI), 256>>>(p_h0, w_ih1, p_gi,
                                                       3 * HID, HID, 3 * HID);
    gru_gates<<<256, 256>>>(dec, p_gh1, b_ih1, b_hh1, st1, nullptr, 1);
    // 6. logits
    logits_mma<<<(VOCAB + 127) / 128, 256, SMEM_TOTAL_LOG>>>(b_out, out);
}

// round 14
// speedup vs baseline: 1.1823x; 1.1234x over previous
#include <cuda_runtime.h>
#include <cuda_fp16.h>
#include <cstdint>
#include <cstddef>

#define HID    1024
#define EMBED  512
#define BATCH  64
#define MAXLEN 1024
#define VOCAB  50257
#define NCHUNK 8
#define KSPL   4
#define AUXY   64          // 512 wout aux blocks / NCHUNK

// ---------------- scratch (no allocations allowed) ----------------
__device__ float  g_dproj[BATCH * HID];
__device__ float  g_dp4[KSPL * BATCH * HID];
__device__ float  g_epart[NCHUNK * MAXLEN * BATCH];
__device__ float  g_alpha[MAXLEN * BATCH];
__device__ float  g_cpart[8 * BATCH * HID];
__device__ float  g_x[BATCH * (EMBED + HID)];
__device__ float  g_gi[KSPL * BATCH * 3 * HID];
__device__ float  g_gh[KSPL * BATCH * 3 * HID];
__device__ float  g_h0[BATCH * HID];
__device__ __half g_bh[HID * HID];                     // w1e^T fp16 [n][k]
__device__ __half g_eh[(size_t)MAXLEN * BATCH * HID];  // enc fp16
__device__ __half g_wh[(size_t)VOCAB * HID];           // w_out fp16 [n][k]
__device__ __half g_h1h[BATCH * HID];                  // h1 fp16

// ---------------- K-split fp32 GEMM body (M=64, 256 threads) ----------------
template <bool BT>
__device__ __forceinline__ void gemm_body(const float* __restrict__ A,
                                          const float* __restrict__ B,
                                          float* __restrict__ C,
                                          int N, int K, int ldc, int nT, int ks) {
    __shared__ float As[64][16];
    __shared__ float Bs[16][64];
    const int Kseg = K / KSPL;
    A += ks * Kseg;                              // row stride stays K
    const float* Bp = BT ? (B + ks * Kseg) : (B + (size_t)ks * Kseg * N);
    C += (size_t)ks * 64 * ldc;
    const int tid = threadIdx.x;
    const int tx  = tid & 15, ty = tid >> 4;
    const int m4  = tid >> 2, kq = tid & 3;

    float acc[4][4] = {};
    for (int k0 = 0; k0 < Kseg; k0 += 16) {
        float4 avv = *(const float4*)(A + (size_t)m4 * K + k0 + kq * 4);
        *(float4*)&As[m4][kq * 4] = avv;
        if (BT) {
            int n = tid >> 2;
            int gn = nT + n;
            float4 bv = make_float4(0.f, 0.f, 0.f, 0.f);
            if (gn < N) bv = *(const float4*)(Bp + (size_t)gn * K + k0 + kq * 4);
            Bs[kq * 4 + 0][n] = bv.x;
            Bs[kq * 4 + 1][n] = bv.y;
            Bs[kq * 4 + 2][n] = bv.z;
            Bs[kq * 4 + 3][n] = bv.w;
        } else {
            #pragma unroll
            for (int e2 = 0; e2 < 4; e2++) {
                int lin = tid + e2 * 256;
                int kk = lin >> 6, n = lin & 63;
                int gn = nT + n;
                Bs[kk][n] = (gn < N) ? Bp[(size_t)(k0 + kk) * N + gn] : 0.f;
            }
        }
        __syncthreads();
        #pragma unroll
        for (int kk = 0; kk < 16; kk++) {
            float4 b4 = *(const float4*)&Bs[kk][tx * 4];
            float bj[4] = {b4.x, b4.y, b4.z, b4.w};
            #pragma unroll
            for (int i = 0; i < 4; i++) {
                float a = As[ty * 4 + i][kk];
                #pragma unroll
                for (int j = 0; j < 4; j++) acc[i][j] = fmaf(a, bj[j], acc[i][j]);
            }
        }
        __syncthreads();
    }
    #pragma unroll
    for (int i = 0; i < 4; i++) {
        int m = ty * 4 + i;
        #pragma unroll
        for (int j = 0; j < 4; j++) {
            int n = nT + tx * 4 + j;
            if (n < N) C[(size_t)m * ldc + n] = acc[i][j];
        }
    }
}

template <bool BT>
__global__ void gemm64_ks(const float* __restrict__ A, const float* __restrict__ B,
                          float* __restrict__ C, int N, int K, int ldc) {
    gemm_body<BT>(A, B, C, N, K, ldc, blockIdx.x * 64, blockIdx.y);
}

// ------- prep_enc_all: aux first (w1e transpose + dproj gemm), then enc->fp16 -------
#define PREP_AUX (1024 + 64)
#define PREP_MAIN 65536
__global__ void prep_enc_all(const float* __restrict__ enc,
                             const float* __restrict__ w1e,
                             const float* __restrict__ w1d,
                             const float* __restrict__ dec) {
    const int bid = blockIdx.x;
    const int tid = threadIdx.x;
    if (bid < 1024) {                    // w1e transpose + fp16
        __shared__ float tile[32][33];
        int k0 = (bid & 31) * 32, n0 = (bid >> 5) * 32;
        int tx = tid & 31, ty = tid >> 5;      // 32 x 8
        for (int i = ty; i < 32; i += 8)
            tile[i][tx] = w1e[(size_t)(k0 + i) * HID + n0 + tx];
        __syncthreads();
        for (int i = ty; i < 32; i += 8)
            g_bh[(size_t)(n0 + i) * HID + k0 + tx] = __float2half_rn(tile[tx][i]);
        return;
    }
    if (bid < PREP_AUX) {                // dproj K-split gemm (16 x 4)
        int g = bid - 1024;
        gemm_body<false>(dec, w1d, g_dp4, HID, HID, HID, (g & 15) * 64, g >> 4);
        return;
    }
    size_t i = ((size_t)(bid - PREP_AUX) * 256 + tid) * 4;   // enc -> fp16
    float4 v = *(const float4*)(enc + i);
    __half h[4];
    h[0] = __float2half_rn(v.x);
    h[1] = __float2half_rn(v.y);
    h[2] = __float2half_rn(v.z);
    h[3] = __float2half_rn(v.w);
    *(uint2*)(g_eh + i) = *(uint2*)h;
}

// ---------------- reduce dproj partials ----------------
__global__ void reduce_dproj() {
    int i = blockIdx.x * 256 + threadIdx.x;
    float s = 0.f;
    #pragma unroll
    for (int p = 0; p < KSPL; p++) s += g_dp4[p * (BATCH * HID) + i];
    g_dproj[i] = s;
}

// ---------------- helpers ----------------
__device__ __forceinline__ uint32_t smem_u32(const void* p) {
    uint32_t a;
    asm("{ .reg .u64 t; cvta.to.shared.u64 t, %1; cvt.u32.u64 %0, t; }" : "=r"(a) : "l"(p));
    return a;
}
__device__ __forceinline__ void cp16(void* s, const void* g) {
    asm volatile("cp.async.cg.shared.global [%0], [%1], 16;"
                 :: "r"(smem_u32(s)), "l"(g));
}
__device__ __forceinline__ void cp_commit() {
    asm volatile("cp.async.commit_group;" ::: "memory");
}
template <int N>
__device__ __forceinline__ void cp_wait() {
    asm volatile("cp.async.wait_group %0;" :: "n"(N) : "memory");
}
__device__ __forceinline__ void mma16816(float* d, const uint32_t* a, const uint32_t* b) {
    asm volatile("mma.sync.aligned.m16n8k16.row.col.f32.f16.f16.f32 "
                 "{%0,%1,%2,%3}, {%4,%5,%6,%7}, {%8,%9}, {%0,%1,%2,%3};"
                 : "+f"(d[0]), "+f"(d[1]), "+f"(d[2]), "+f"(d[3])
                 : "r"(a[0]), "r"(a[1]), "r"(a[2]), "r"(a[3]),
                   "r"(b[0]), "r"(b[1]));
}
__device__ __forceinline__ void ldsm4(uint32_t* r, uint32_t addr) {
    asm volatile("ldmatrix.sync.aligned.m8n8.x4.shared.b16 {%0,%1,%2,%3}, [%4];"
                 : "=r"(r[0]), "=r"(r[1]), "=r"(r[2]), "=r"(r[3]) : "r"(addr));
}

// ================= attention GEMM (+ wout conversion aux) =================
#define ASTRIDE 72
#define MATH (128 * ASTRIDE)
#define STAGE_BYTES (2 * MATH * 2)
#define NSTAGE 4
#define SMEM_TOTAL_ATT (NSTAGE * STAGE_BYTES)
#define KC 64
#define KT (HID / KC)

__global__ void __launch_bounds__(512, 1)
attn_mma(const float* __restrict__ w2, const float* __restrict__ wout) {
    extern __shared__ char smem[];
    const int tid = threadIdx.x;

    if (blockIdx.y >= 512) {
        const int aux = (blockIdx.y - 512) * NCHUNK + blockIdx.x;   // 0..511
        const size_t total4 = (size_t)VOCAB * HID / 4;
        for (size_t i = (size_t)aux * 512 + tid; i < total4; i += (size_t)512 * 512) {
            float4 v = *(const float4*)(wout + i * 4);
            __half h[4];
            h[0] = __float2half_rn(v.x);
            h[1] = __float2half_rn(v.y);
            h[2] = __float2half_rn(v.z);
            h[3] = __float2half_rn(v.w);
            *(uint2*)(g_wh + i * 4) = *(uint2*)h;
        }
        return;
    }

    const uint32_t sbase = smem_u32(smem);
    const int bn = blockIdx.x;
    const int mt = blockIdx.y;
    const int wid = tid >> 5, lane = tid & 31;
    const int wm = wid >> 2, wn = wid & 3;
    const int qr = lane >> 2, qc = lane & 3;

    const __half* gAh = g_eh + (size_t)mt * 128 * HID;
    const __half* gBh = g_bh + (size_t)(bn * 128) * HID;

    const int lr = tid >> 2, lc = tid & 3;

    auto issue_load = [&](int kt) {
        char* base = smem + (kt % NSTAGE) * STAGE_BYTES;
        __half* sAh = (__half*)base;
        __half* sBh = sAh + MATH;
        #pragma unroll
        for (int i = 0; i < 2; i++) {
            int c = lc + i * 4;
            size_t go = (size_t)lr * HID + kt * KC + c * 8;
            int so = lr * ASTRIDE + c * 8;
            cp16(sAh + so, gAh + go);
            cp16(sBh + so, gBh + go);
        }
        cp_commit();
    };

    int offA[2];
    #pragma unroll
    for (int m = 0; m < 2; m++)
        offA[m] = ((wm * 32 + m * 16 + (lane & 15)) * ASTRIDE + (lane >> 4) * 8) * 2;
    int offB[2];
    #pragma unroll
    for (int j = 0; j < 2; j++)
        offB[j] = ((wn * 32 + (2 * j + (lane >> 4)) * 8 + (lane & 7)) * ASTRIDE
                   + ((lane >> 3) & 1) * 8) * 2;

    float acc[2][4][4] = {};

    auto compute = [&](int kt) {
        const uint32_t base = sbase + (kt % NSTAGE) * STAGE_BYTES;
        const uint32_t uAh = base;
        const uint32_t uBh = base + MATH * 2;
        #pragma unroll
        for (int ks = 0; ks < KC; ks += 16) {
            uint32_t ah[2][4], bh[4][2];
            #pragma unroll
            for (int m = 0; m < 2; m++)
                ldsm4(ah[m], uAh + offA[m] + ks * 2);
            #pragma unroll
            for (int j = 0; j < 2; j++) {
                uint32_t r[4];
                ldsm4(r, uBh + offB[j] + ks * 2);
                bh[2 * j][0] = r[0]; bh[2 * j][1] = r[1];
                bh[2 * j + 1][0] = r[2]; bh[2 * j + 1][1] = r[3];
            }
            #pragma unroll
            for (int m = 0; m < 2; m++)
                #pragma unroll
                for (int n = 0; n < 4; n++) mma16816(acc[m][n], ah[m], bh[n]);
        }
    };

    issue_load(0);
    issue_load(1);
    issue_load(2);
    for (int kt = 0; kt < KT; kt++) {
        cp_wait<2>();
        __syncthreads();
        if (kt + 3 < KT) issue_load(kt + 3);
        else cp_commit();
        compute(kt);
    }

    float rsum[2][2] = {};
    #pragma unroll
    for (int m = 0; m < 2; m++) {
        #pragma unroll
        for (int n = 0; n < 4; n++) {
            int ng0 = bn * 128 + wn * 32 + n * 8 + qc * 2;
            float w20 = w2[ng0], w21 = w2[ng0 + 1];
            #pragma unroll
            for (int pr = 0; pr < 2; pr++) {
                int row_local = wm * 32 + m * 16 + qr + pr * 8;
                int b = row_local & 63;
                const float* dp = g_dproj + (size_t)b * HID + ng0;
                rsum[m][pr] += tanhf(acc[m][n][pr * 2 + 0] + dp[0]) * w20
                             + tanhf(acc[m][n][pr * 2 + 1] + dp[1]) * w21;
            }
        }
    }
    #pragma unroll
    for (int m = 0; m < 2; m++)
        #pragma unroll
        for (int pr = 0; pr < 2; pr++) {
            float v = rsum[m][pr];
            v += __shfl_xor_sync(0xffffffffu, v, 1);
            v += __shfl_xor_sync(0xffffffffu, v, 2);
            rsum[m][pr] = v;
        }
    float* part = (float*)smem;
    __syncthreads();
    if (qc == 0) {
        #pragma unroll
        for (int m = 0; m < 2; m++)
            #pragma unroll
            for (int pr = 0; pr < 2; pr++)
                part[(wm * 32 + m * 16 + qr + pr * 8) * 4 + wn] = rsum[m][pr];
    }
    __syncthreads();
    if (tid < 128) {
        float e = part[tid * 4 + 0] + part[tid * 4 + 1] + part[tid * 4 + 2] + part[tid * 4 + 3];
        g_epart[(size_t)bn * (MAXLEN * BATCH) + mt * 128 + tid] = e;
    }
}

// ================= logits GEMM: single-pass fp16 =================
#define L_ASTR 72
#define L_MA (64 * L_ASTR)
#define L_MB (128 * L_ASTR)
#define L_STAGE ((L_MA + L_MB) * 2)
#define L_NSTAGE 4
#define SMEM_TOTAL_LOG (L_NSTAGE * L_STAGE)

__global__ void __launch_bounds__(256, 1)
logits_mma(const float* __restrict__ bias, float* __restrict__ out) {
    extern __shared__ char smem[];
    const uint32_t sbase = smem_u32(smem);
    const int n0 = blockIdx.x * 128;
    const int tid = threadIdx.x;
    const int wid = tid >> 5, lane = tid & 31;
    const int wm = wid >> 2, wn = wid & 3;
    const int qr = lane >> 2, qc = lane & 3;

    const int ar = tid >> 2, ac = tid & 3;
    const int br = tid >> 1, bc0 = (tid & 1) * 4;

    auto issue_load = [&](int kt) {
        char* base = smem + (kt % L_NSTAGE) * L_STAGE;
        __half* sAh = (__half*)base;
        __half* sB  = sAh + L_MA;
        #pragma unroll
        for (int i = 0; i < 2; i++) {
            int c = ac + i * 4;
            size_t go = (size_t)ar * HID + kt * KC + c * 8;
            cp16(sAh + ar * L_ASTR + c * 8, g_h1h + go);
        }
        int gn = n0 + br; if (gn >= VOCAB) gn = VOCAB - 1;
        #pragma unroll
        for (int i = 0; i < 4; i++) {
            int c = bc0 + i;
            cp16(sB + br * L_ASTR + c * 8, g_wh + (size_t)gn * HID + kt * KC + c * 8);
        }
        cp_commit();
    };

    int offA[2];
    #pragma unroll
    for (int m = 0; m < 2; m++)
        offA[m] = ((wm * 32 + m * 16 + (lane & 15)) * L_ASTR + (lane >> 4) * 8) * 2;
    int offB[2];
    #pragma unroll
    for (int j = 0; j < 2; j++)
        offB[j] = ((wn * 32 + (2 * j + (lane >> 4)) * 8 + (lane & 7)) * L_ASTR
                   + ((lane >> 3) & 1) * 8) * 2;

    float acc[2][4][4] = {};

    auto compute = [&](int kt) {
        const uint32_t base = sbase + (kt % L_NSTAGE) * L_STAGE;
        const uint32_t uAh = base;
        const uint32_t uB  = base + L_MA * 2;
        #pragma unroll
        for (int ks = 0; ks < KC; ks += 16) {
            uint32_t ah[2][4], bb[4][2];
            #pragma unroll
            for (int m = 0; m < 2; m++)
                ldsm4(ah[m], uAh + offA[m] + ks * 2);
            #pragma unroll
            for (int j = 0; j < 2; j++) {
                uint32_t r[4];
                ldsm4(r, uB + offB[j] + ks * 2);
                bb[2 * j][0] = r[0]; bb[2 * j][1] = r[1];
                bb[2 * j + 1][0] = r[2]; bb[2 * j + 1][1] = r[3];
            }
            #pragma unroll
            for (int m = 0; m < 2; m++)
                #pragma unroll
                for (int n = 0; n < 4; n++) mma16816(acc[m][n], ah[m], bb[n]);
        }
    };

    issue_load(0);
    issue_load(1);
    issue_load(2);
    for (int kt = 0; kt < KT; kt++) {
        cp_wait<2>();
        __syncthreads();
        if (kt + 3 < KT) issue_load(kt + 3);
        else cp_commit();
        compute(kt);
    }

    #pragma unroll
    for (int m = 0; m < 2; m++) {
        #pragma unroll
        for (int n = 0; n < 4; n++) {
            int col = n0 + wn * 32 + n * 8 + qc * 2;
            #pragma unroll
            for (int pr = 0; pr < 2; pr++) {
                int row = wm * 32 + m * 16 + qr + pr * 8;
                if (col < VOCAB)
                    out[(size_t)row * VOCAB + col] = acc[m][n][pr * 2 + 0] + bias[col];
                if (col + 1 < VOCAB)
                    out[(size_t)row * VOCAB + col + 1] = acc[m][n][pr * 2 + 1] + bias[col + 1];
            }
        }
    }
}

// ---------------- softmax over t ----------------
__global__ void softmax_kernel() {
    const int b = blockIdx.x;
    __shared__ float es[MAXLEN];
    __shared__ float red[256];
    const int tid = threadIdx.x;

    float mx = -1e30f;
    for (int t = tid; t < MAXLEN; t += 256) {
        float s = 0.f;
        #pragma unroll
        for (int p = 0; p < NCHUNK; p++) s += g_epart[p * (MAXLEN * BATCH) + t * 64 + b];
        es[t] = s;
        mx = fmaxf(mx, s);
    }
    red[tid] = mx; __syncthreads();
    for (int s2 = 128; s2; s2 >>= 1) {
        if (tid < s2) red[tid] = fmaxf(red[tid], red[tid + s2]);
        __syncthreads();
    }
    mx = red[0]; __syncthreads();

    float sum = 0.f;
    for (int t = tid; t < MAXLEN; t += 256) {
        float v = __expf(es[t] - mx);
        es[t] = v;
        sum += v;
    }
    red[tid] = sum; __syncthreads();
    for (int s2 = 128; s2; s2 >>= 1) {
        if (tid < s2) red[tid] += red[tid + s2];
        __syncthreads();
    }
    float inv = 1.f / red[0];
    for (int t = tid; t < MAXLEN; t += 256) g_alpha[t * 64 + b] = es[t] * inv;
}

// ---------------- context (fp16 enc) ----------------
__global__ void context_kernel() {
    const int b = blockIdx.x, seg = blockIdx.y;
    const int h = threadIdx.x;
    float acc = 0.f;
    #pragma unroll 4
    for (int t = seg * 128; t < (seg + 1) * 128; t++)
        acc = fmaf(g_alpha[t * 64 + b],
                   __half2float(g_eh[((size_t)t * 64 + b) * HID + h]), acc);
    g_cpart[(seg * BATCH + b) * HID + h] = acc;
}

// ---------------- x = concat(embedding[cur], c) ----------------
__global__ void build_x(const int* __restrict__ cur, const float* __restrict__ emb) {
    const int b = blockIdx.x, tid = threadIdx.x;
    const int tok = cur[b];
    for (int k = tid; k < EMBED; k += 512)
        g_x[b * (EMBED + HID) + k] = emb[(size_t)tok * EMBED + k];
    for (int k = tid; k < HID; k += 512) {
        float s = 0.f;
        #pragma unroll
        for (int p = 0; p < 8; p++) s += g_cpart[(p * BATCH + b) * HID + k];
        g_x[b * (EMBED + HID) + EMBED + k] = s;
    }
}

// ---------------- GRU gates (reduces K-split partials; optional fp16 h1 out) ----------------
__global__ void gru_gates(const float* __restrict__ hprev,
                          const float* __restrict__ b_ih,
                          const float* __restrict__ b_hh,
                          float* __restrict__ out1, float* __restrict__ out2,
                          int write_h1) {
    const int idx = blockIdx.x * 256 + threadIdx.x;
    const int b = idx >> 10, q = idx & 1023;
    const int base = b * 3072 + q;
    float ir = b_ih[q], iz = b_ih[q + 1024], in_ = b_ih[q + 2048];
    float hr = b_hh[q], hz = b_hh[q + 1024], hn = b_hh[q + 2048];
    #pragma unroll
    for (int p = 0; p < KSPL; p++) {
        const float* gi = g_gi + p * (BATCH * 3 * HID);
        const float* gh = g_gh + p * (BATCH * 3 * HID);
        ir += gi[base];        hr += gh[base];
        iz += gi[base + 1024]; hz += gh[base + 1024];
        in_ += gi[base + 2048]; hn += gh[base + 2048];
    }
    float r = 1.f / (1.f + __expf(-(ir + hr)));
    float z = 1.f / (1.f + __expf(-(iz + hz)));
    float n = tanhf(in_ + r * hn);
    float h = (1.f - z) * n + z * hprev[idx];
    out1[idx] = h;
    if (out2) out2[idx] = h;
    if (write_h1) g_h1h[idx] = __float2half_rn(h);
}

// ---------------- launch (single stream; graph-capture safe) ----------------
extern "C" void kernel_launch(void* const* d_in, const int* in_sizes, int n_in,
                              void* d_out, int out_size) {
    const int*   cur    = (const int*)d_in[0];
    const float* state  = (const float*)d_in[1];
    const float* enc    = (const float*)d_in[2];
    const float* emb    = (const float*)d_in[3];
    const float* w_att1 = (const float*)d_in[4];
    const float* w_att2 = (const float*)d_in[5];
    const float* w_ih0  = (const float*)d_in[6];
    const float* w_hh0  = (const float*)d_in[7];
    const float* b_ih0  = (const float*)d_in[8];
    const float* b_hh0  = (const float*)d_in[9];
    const float* w_ih1  = (const float*)d_in[10];
    const float* w_hh1  = (const float*)d_in[11];
    const float* b_ih1  = (const float*)d_in[12];
    const float* b_hh1  = (const float*)d_in[13];
    const float* w_out  = (const float*)d_in[14];
    const float* b_out  = (const float*)d_in[15];

    float* out = (float*)d_out;
    float* st0 = out + (size_t)BATCH * VOCAB;
    float* st1 = st0 + BATCH * HID;

    float *p_x, *p_gi, *p_gh, *p_h0;
    cudaGetSymbolAddress((void**)&p_x,  g_x);
    cudaGetSymbolAddress((void**)&p_gi, g_gi);
    cudaGetSymbolAddress((void**)&p_gh, g_gh);
    cudaGetSymbolAddress((void**)&p_h0, g_h0);

    cudaFuncSetAttribute(attn_mma, cudaFuncAttributeMaxDynamicSharedMemorySize,
                         SMEM_TOTAL_ATT);
    cudaFuncSetAttribute(logits_mma, cudaFuncAttributeMaxDynamicSharedMemorySize,
                         SMEM_TOTAL_LOG);

    const float* dec = state + (size_t)BATCH * HID;

    // 1. prep: w1e transpose + dproj gemm (aux, first) + enc->fp16 (main)
    prep_enc_all<<<PREP_AUX + PREP_MAIN, 256>>>(enc, w_att1,
                                                w_att1 + (size_t)HID * HID, dec);
    reduce_dproj<<<BATCH * HID / 256, 256>>>();
    // 2. attention energies (+ wout->fp16 aux)
    attn_mma<<<dim3(NCHUNK, 512 + AUXY), 512, SMEM_TOTAL_ATT>>>(w_att2, w_out);
    // 3. softmax
    softmax_kernel<<<BATCH, 256>>>();
    // 4. context (fp16 enc)
    context_kernel<<<dim3(BATCH, 8), 1024>>>();
    // 5. x = concat(emb, c)
    build_x<<<BATCH, 512>>>(cur, emb);
    // 6. GRU layer 0
    gemm64_ks<true><<<dim3(48, KSPL), 256>>>(p_x,   w_ih0, p_gi, 3 * HID, EMBED + HID, 3 * HID);
    gemm64_ks<true><<<dim3(48, KSPL), 256>>>(state, w_hh0, p_gh, 3 * HID, HID,         3 * HID);
    gru_gates<<<256, 256>>>(state, b_ih0, b_hh0, st0, p_h0, 0);
    // 7. GRU layer 1 (writes fp16 h1 for logits)
    gemm64_ks<true><<<dim3(48, KSPL), 256>>>(p_h0, w_ih1, p_gi, 3 * HID, HID, 3 * HID);
    gemm64_ks<true><<<dim3(48, KSPL), 256>>>(dec,  w_hh1, p_gh, 3 * HID, HID, 3 * HID);
    gru_gates<<<256, 256>>>(dec, b_ih1, b_hh1, st1, nullptr, 1);
    // 8. logits
    logits_mma<<<(VOCAB + 127) / 128, 256, SMEM_TOTAL_LOG>>>(b_out, out);
}

// round 16
// speedup vs baseline: 1.2794x; 1.0821x over previous
#include <cuda_runtime.h>
#include <cuda_fp16.h>
#include <cstdint>
#include <cstddef>

#define HID    1024
#define EMBED  512
#define BATCH  64
#define MAXLEN 1024
#define VOCAB  50257
#define NCHUNK 8
#define KSPL   4
#define AUXY   64          // 512 wout aux blocks / NCHUNK
#define PREP_MAIN_BLOCKS ((MAXLEN * BATCH * HID) / (256 * 4))

// ---------------- scratch (no allocations allowed) ----------------
__device__ float  g_dproj[BATCH * HID];
__device__ float  g_dp4[KSPL * BATCH * HID];
__device__ float  g_epart[NCHUNK * MAXLEN * BATCH];
__device__ float  g_alpha[MAXLEN * BATCH];
__device__ float  g_cpart[8 * BATCH * HID];
__device__ float  g_x[BATCH * (EMBED + HID)];
__device__ float  g_gi[KSPL * BATCH * 3 * HID];
__device__ float  g_gh[KSPL * BATCH * 3 * HID];
__device__ float  g_h0[BATCH * HID];
__device__ __half g_bh[HID * HID];                     // w1e^T fp16 [n][k]
__device__ __half g_eh[(size_t)MAXLEN * BATCH * HID];  // enc fp16
__device__ __half g_wh[(size_t)VOCAB * HID];           // w_out fp16 [n][k]
__device__ __half g_h1h[BATCH * HID];                  // h1 fp16

// ---------------- K-split fp32 GEMM body (M=64, 256 threads, KSPL=4) ----------------
template <bool BT>
__device__ __forceinline__ void gemm_body(const float* __restrict__ A,
                                          const float* __restrict__ B,
                                          float* __restrict__ C,
                                          int N, int K, int ldc, int nT, int ks) {
    __shared__ float As[64][16];
    __shared__ float Bs[16][64];
    const int Kseg = K / KSPL;
    A += ks * Kseg;                              // row stride stays K
    const float* Bp = BT ? (B + ks * Kseg) : (B + (size_t)ks * Kseg * N);
    C += (size_t)ks * 64 * ldc;
    const int tid = threadIdx.x;
    const int tx  = tid & 15, ty = tid >> 4;
    const int m4  = tid >> 2, kq = tid & 3;

    float acc[4][4] = {};
    for (int k0 = 0; k0 < Kseg; k0 += 16) {
        float4 avv = *(const float4*)(A + (size_t)m4 * K + k0 + kq * 4);
        *(float4*)&As[m4][kq * 4] = avv;
        if (BT) {
            int n = tid >> 2;
            int gn = nT + n;
            float4 bv = make_float4(0.f, 0.f, 0.f, 0.f);
            if (gn < N) bv = *(const float4*)(Bp + (size_t)gn * K + k0 + kq * 4);
            Bs[kq * 4 + 0][n] = bv.x;
            Bs[kq * 4 + 1][n] = bv.y;
            Bs[kq * 4 + 2][n] = bv.z;
            Bs[kq * 4 + 3][n] = bv.w;
        } else {
            #pragma unroll
            for (int e2 = 0; e2 < 4; e2++) {
                int lin = tid + e2 * 256;
                int kk = lin >> 6, n = lin & 63;
                int gn = nT + n;
                Bs[kk][n] = (gn < N) ? Bp[(size_t)(k0 + kk) * N + gn] : 0.f;
            }
        }
        __syncthreads();
        #pragma unroll
        for (int kk = 0; kk < 16; kk++) {
            float4 b4 = *(const float4*)&Bs[kk][tx * 4];
            float bj[4] = {b4.x, b4.y, b4.z, b4.w};
            #pragma unroll
            for (int i = 0; i < 4; i++) {
                float a = As[ty * 4 + i][kk];
                #pragma unroll
                for (int j = 0; j < 4; j++) acc[i][j] = fmaf(a, bj[j], acc[i][j]);
            }
        }
        __syncthreads();
    }
    #pragma unroll
    for (int i = 0; i < 4; i++) {
        int m = ty * 4 + i;
        #pragma unroll
        for (int j = 0; j < 4; j++) {
            int n = nT + tx * 4 + j;
            if (n < N) C[(size_t)m * ldc + n] = acc[i][j];
        }
    }
}

// ---------------- merged GRU projections: gi (blocks 0..47) + gh (48..95) ----------------
__global__ void gru_gemms(const float* __restrict__ A1, const float* __restrict__ B1,
                          float* __restrict__ C1, int K1,
                          const float* __restrict__ A2, const float* __restrict__ B2,
                          float* __restrict__ C2, int K2) {
    if (blockIdx.x < 48)
        gemm_body<true>(A1, B1, C1, 3 * HID, K1, 3 * HID, blockIdx.x * 64, blockIdx.y);
    else
        gemm_body<true>(A2, B2, C2, 3 * HID, K2, 3 * HID, (blockIdx.x - 48) * 64, blockIdx.y);
}

// ---------------- merged prep: w1e transpose (0..1023) + dproj gemm (1024..1087) ----------------
__global__ void prep_w1e_dproj(const float* __restrict__ w1e,
                               const float* __restrict__ w1d,
                               const float* __restrict__ dec) {
    const int bid = blockIdx.x;
    const int tid = threadIdx.x;
    if (bid < 1024) {
        __shared__ float tile[32][33];
        int k0 = (bid & 31) * 32, n0 = (bid >> 5) * 32;
        int tx = tid & 31, ty = tid >> 5;      // 32 x 8
        for (int i = ty; i < 32; i += 8)
            tile[i][tx] = w1e[(size_t)(k0 + i) * HID + n0 + tx];
        __syncthreads();
        for (int i = ty; i < 32; i += 8)
            g_bh[(size_t)(n0 + i) * HID + k0 + tx] = __float2half_rn(tile[tx][i]);
        return;
    }
    int g = bid - 1024;                        // 0..63
    gemm_body<false>(dec, w1d, g_dp4, HID, HID, HID, (g & 15) * 64, g >> 4);
}

// ---------------- prep: fp16 enc_states ----------------
__global__ void prep_enc(const float* __restrict__ enc) {
    size_t i = ((size_t)blockIdx.x * 256 + threadIdx.x) * 4;
    float4 v = *(const float4*)(enc + i);
    __half h[4];
    h[0] = __float2half_rn(v.x);
    h[1] = __float2half_rn(v.y);
    h[2] = __float2half_rn(v.z);
    h[3] = __float2half_rn(v.w);
    *(uint2*)(g_eh + i) = *(uint2*)h;
}

// ---------------- reduce dproj partials ----------------
__global__ void reduce_dproj() {
    int i = blockIdx.x * 256 + threadIdx.x;
    float s = 0.f;
    #pragma unroll
    for (int p = 0; p < KSPL; p++) s += g_dp4[p * (BATCH * HID) + i];
    g_dproj[i] = s;
}

// ---------------- helpers ----------------
__device__ __forceinline__ uint32_t smem_u32(const void* p) {
    uint32_t a;
    asm("{ .reg .u64 t; cvta.to.shared.u64 t, %1; cvt.u32.u64 %0, t; }" : "=r"(a) : "l"(p));
    return a;
}
__device__ __forceinline__ void cp16(void* s, const void* g) {
    asm volatile("cp.async.cg.shared.global [%0], [%1], 16;"
                 :: "r"(smem_u32(s)), "l"(g));
}
__device__ __forceinline__ void cp_commit() {
    asm volatile("cp.async.commit_group;" ::: "memory");
}
template <int N>
__device__ __forceinline__ void cp_wait() {
    asm volatile("cp.async.wait_group %0;" :: "n"(N) : "memory");
}
__device__ __forceinline__ void mma16816(float* d, const uint32_t* a, const uint32_t* b) {
    asm volatile("mma.sync.aligned.m16n8k16.row.col.f32.f16.f16.f32 "
                 "{%0,%1,%2,%3}, {%4,%5,%6,%7}, {%8,%9}, {%0,%1,%2,%3};"
                 : "+f"(d[0]), "+f"(d[1]), "+f"(d[2]), "+f"(d[3])
                 : "r"(a[0]), "r"(a[1]), "r"(a[2]), "r"(a[3]),
                   "r"(b[0]), "r"(b[1]));
}
__device__ __forceinline__ void ldsm4(uint32_t* r, uint32_t addr) {
    asm volatile("ldmatrix.sync.aligned.m8n8.x4.shared.b16 {%0,%1,%2,%3}, [%4];"
                 : "=r"(r[0]), "=r"(r[1]), "=r"(r[2]), "=r"(r[3]) : "r"(addr));
}

// ================= attention GEMM (+ wout conversion aux) =================
#define ASTRIDE 72
#define MATH (128 * ASTRIDE)
#define STAGE_BYTES (2 * MATH * 2)
#define NSTAGE 4
#define SMEM_TOTAL_ATT (NSTAGE * STAGE_BYTES)
#define KC 64
#define KT (HID / KC)

__global__ void __launch_bounds__(512, 1)
attn_mma(const float* __restrict__ w2, const float* __restrict__ wout) {
    extern __shared__ char smem[];
    const int tid = threadIdx.x;

    if (blockIdx.y >= 512) {
        const int aux = (blockIdx.y - 512) * NCHUNK + blockIdx.x;   // 0..511
        const size_t total4 = (size_t)VOCAB * HID / 4;
        for (size_t i = (size_t)aux * 512 + tid; i < total4; i += (size_t)512 * 512) {
            float4 v = *(const float4*)(wout + i * 4);
            __half h[4];
            h[0] = __float2half_rn(v.x);
            h[1] = __float2half_rn(v.y);
            h[2] = __float2half_rn(v.z);
            h[3] = __float2half_rn(v.w);
            *(uint2*)(g_wh + i * 4) = *(uint2*)h;
        }
        return;
    }

    const uint32_t sbase = smem_u32(smem);
    const int bn = blockIdx.x;
    const int mt = blockIdx.y;
    const int wid = tid >> 5, lane = tid & 31;
    const int wm = wid >> 2, wn = wid & 3;
    const int qr = lane >> 2, qc = lane & 3;

    const __half* gAh = g_eh + (size_t)mt * 128 * HID;
    const __half* gBh = g_bh + (size_t)(bn * 128) * HID;

    const int lr = tid >> 2, lc = tid & 3;

    auto issue_load = [&](int kt) {
        char* base = smem + (kt % NSTAGE) * STAGE_BYTES;
        __half* sAh = (__half*)base;
        __half* sBh = sAh + MATH;
        #pragma unroll
        for (int i = 0; i < 2; i++) {
            int c = lc + i * 4;
            size_t go = (size_t)lr * HID + kt * KC + c * 8;
            int so = lr * ASTRIDE + c * 8;
            cp16(sAh + so, gAh + go);
            cp16(sBh + so, gBh + go);
        }
        cp_commit();
    };

    int offA[2];
    #pragma unroll
    for (int m = 0; m < 2; m++)
        offA[m] = ((wm * 32 + m * 16 + (lane & 15)) * ASTRIDE + (lane >> 4) * 8) * 2;
    int offB[2];
    #pragma unroll
    for (int j = 0; j < 2; j++)
        offB[j] = ((wn * 32 + (2 * j + (lane >> 4)) * 8 + (lane & 7)) * ASTRIDE
                   + ((lane >> 3) & 1) * 8) * 2;

    float acc[2][4][4] = {};

    auto compute = [&](int kt) {
        const uint32_t base = sbase + (kt % NSTAGE) * STAGE_BYTES;
        const uint32_t uAh = base;
        const uint32_t uBh = base + MATH * 2;
        #pragma unroll
        for (int ks = 0; ks < KC; ks += 16) {
            uint32_t ah[2][4], bh[4][2];
            #pragma unroll
            for (int m = 0; m < 2; m++)
                ldsm4(ah[m], uAh + offA[m] + ks * 2);
            #pragma unroll
            for (int j = 0; j < 2; j++) {
                uint32_t r[4];
                ldsm4(r, uBh + offB[j] + ks * 2);
                bh[2 * j][0] = r[0]; bh[2 * j][1] = r[1];
                bh[2 * j + 1][0] = r[2]; bh[2 * j + 1][1] = r[3];
            }
            #pragma unroll
            for (int m = 0; m < 2; m++)
                #pragma unroll
                for (int n = 0; n < 4; n++) mma16816(acc[m][n], ah[m], bh[n]);
        }
    };

    issue_load(0);
    issue_load(1);
    issue_load(2);
    for (int kt = 0; kt < KT; kt++) {
        cp_wait<2>();
        __syncthreads();
        if (kt + 3 < KT) issue_load(kt + 3);
        else cp_commit();
        compute(kt);
    }

    float rsum[2][2] = {};
    #pragma unroll
    for (int m = 0; m < 2; m++) {
        #pragma unroll
        for (int n = 0; n < 4; n++) {
            int ng0 = bn * 128 + wn * 32 + n * 8 + qc * 2;
            float w20 = w2[ng0], w21 = w2[ng0 + 1];
            #pragma unroll
            for (int pr = 0; pr < 2; pr++) {
                int row_local = wm * 32 + m * 16 + qr + pr * 8;
                int b = row_local & 63;
                const float* dp = g_dproj + (size_t)b * HID + ng0;
                rsum[m][pr] += tanhf(acc[m][n][pr * 2 + 0] + dp[0]) * w20
                             + tanhf(acc[m][n][pr * 2 + 1] + dp[1]) * w21;
            }
        }
    }
    #pragma unroll
    for (int m = 0; m < 2; m++)
        #pragma unroll
        for (int pr = 0; pr < 2; pr++) {
            float v = rsum[m][pr];
            v += __shfl_xor_sync(0xffffffffu, v, 1);
            v += __shfl_xor_sync(0xffffffffu, v, 2);
            rsum[m][pr] = v;
        }
    float* part = (float*)smem;
    __syncthreads();
    if (qc == 0) {
        #pragma unroll
        for (int m = 0; m < 2; m++)
            #pragma unroll
            for (int pr = 0; pr < 2; pr++)
                part[(wm * 32 + m * 16 + qr + pr * 8) * 4 + wn] = rsum[m][pr];
    }
    __syncthreads();
    if (tid < 128) {
        float e = part[tid * 4 + 0] + part[tid * 4 + 1] + part[tid * 4 + 2] + part[tid * 4 + 3];
        g_epart[(size_t)bn * (MAXLEN * BATCH) + mt * 128 + tid] = e;
    }
}

// ================= logits GEMM: single-pass fp16 =================
#define L_ASTR 72
#define L_MA (64 * L_ASTR)
#define L_MB (128 * L_ASTR)
#define L_STAGE ((L_MA + L_MB) * 2)
#define L_NSTAGE 4
#define SMEM_TOTAL_LOG (L_NSTAGE * L_STAGE)

__global__ void __launch_bounds__(256, 1)
logits_mma(const float* __restrict__ bias, float* __restrict__ out) {
    extern __shared__ char smem[];
    const uint32_t sbase = smem_u32(smem);
    const int n0 = blockIdx.x * 128;
    const int tid = threadIdx.x;
    const int wid = tid >> 5, lane = tid & 31;
    const int wm = wid >> 2, wn = wid & 3;
    const int qr = lane >> 2, qc = lane & 3;

    const int ar = tid >> 2, ac = tid & 3;
    const int br = tid >> 1, bc0 = (tid & 1) * 4;

    auto issue_load = [&](int kt) {
        char* base = smem + (kt % L_NSTAGE) * L_STAGE;
        __half* sAh = (__half*)base;
        __half* sB  = sAh + L_MA;
        #pragma unroll
        for (int i = 0; i < 2; i++) {
            int c = ac + i * 4;
            size_t go = (size_t)ar * HID + kt * KC + c * 8;
            cp16(sAh + ar * L_ASTR + c * 8, g_h1h + go);
        }
        int gn = n0 + br; if (gn >= VOCAB) gn = VOCAB - 1;
        #pragma unroll
        for (int i = 0; i < 4; i++) {
            int c = bc0 + i;
            cp16(sB + br * L_ASTR + c * 8, g_wh + (size_t)gn * HID + kt * KC + c * 8);
        }
        cp_commit();
    };

    int offA[2];
    #pragma unroll
    for (int m = 0; m < 2; m++)
        offA[m] = ((wm * 32 + m * 16 + (lane & 15)) * L_ASTR + (lane >> 4) * 8) * 2;
    int offB[2];
    #pragma unroll
    for (int j = 0; j < 2; j++)
        offB[j] = ((wn * 32 + (2 * j + (lane >> 4)) * 8 + (lane & 7)) * L_ASTR
                   + ((lane >> 3) & 1) * 8) * 2;

    float acc[2][4][4] = {};

    auto compute = [&](int kt) {
        const uint32_t base = sbase + (kt % L_NSTAGE) * L_STAGE;
        const uint32_t uAh = base;
        const uint32_t uB  = base + L_MA * 2;
        #pragma unroll
        for (int ks = 0; ks < KC; ks += 16) {
            uint32_t ah[2][4], bb[4][2];
            #pragma unroll
            for (int m = 0; m < 2; m++)
                ldsm4(ah[m], uAh + offA[m] + ks * 2);
            #pragma unroll
            for (int j = 0; j < 2; j++) {
                uint32_t r[4];
                ldsm4(r, uB + offB[j] + ks * 2);
                bb[2 * j][0] = r[0]; bb[2 * j][1] = r[1];
                bb[2 * j + 1][0] = r[2]; bb[2 * j + 1][1] = r[3];
            }
            #pragma unroll
            for (int m = 0; m < 2; m++)
                #pragma unroll
                for (int n = 0; n < 4; n++) mma16816(acc[m][n], ah[m], bb[n]);
        }
    };

    issue_load(0);
    issue_load(1);
    issue_load(2);
    for (int kt = 0; kt < KT; kt++) {
        cp_wait<2>();
        __syncthreads();
        if (kt + 3 < KT) issue_load(kt + 3);
        else cp_commit();
        compute(kt);
    }

    #pragma unroll
    for (int m = 0; m < 2; m++) {
        #pragma unroll
        for (int n = 0; n < 4; n++) {
            int col = n0 + wn * 32 + n * 8 + qc * 2;
            #pragma unroll
            for (int pr = 0; pr < 2; pr++) {
                int row = wm * 32 + m * 16 + qr + pr * 8;
                if (col < VOCAB)
                    out[(size_t)row * VOCAB + col] = acc[m][n][pr * 2 + 0] + bias[col];
                if (col + 1 < VOCAB)
                    out[(size_t)row * VOCAB + col + 1] = acc[m][n][pr * 2 + 1] + bias[col + 1];
            }
        }
    }
}

// ---------------- softmax over t ----------------
__global__ void softmax_kernel() {
    const int b = blockIdx.x;
    __shared__ float es[MAXLEN];
    __shared__ float red[256];
    const int tid = threadIdx.x;

    float mx = -1e30f;
    for (int t = tid; t < MAXLEN; t += 256) {
        float s = 0.f;
        #pragma unroll
        for (int p = 0; p < NCHUNK; p++) s += g_epart[p * (MAXLEN * BATCH) + t * 64 + b];
        es[t] = s;
        mx = fmaxf(mx, s);
    }
    red[tid] = mx; __syncthreads();
    for (int s2 = 128; s2; s2 >>= 1) {
        if (tid < s2) red[tid] = fmaxf(red[tid], red[tid + s2]);
        __syncthreads();
    }
    mx = red[0]; __syncthreads();

    float sum = 0.f;
    for (int t = tid; t < MAXLEN; t += 256) {
        float v = __expf(es[t] - mx);
        es[t] = v;
        sum += v;
    }
    red[tid] = sum; __syncthreads();
    for (int s2 = 128; s2; s2 >>= 1) {
        if (tid < s2) red[tid] += red[tid + s2];
        __syncthreads();
    }
    float inv = 1.f / red[0];
    for (int t = tid; t < MAXLEN; t += 256) g_alpha[t * 64 + b] = es[t] * inv;
}

// ---------------- context (fp16 enc) ----------------
__global__ void context_kernel() {
    const int b = blockIdx.x, seg = blockIdx.y;
    const int h = threadIdx.x;
    float acc = 0.f;
    #pragma unroll 4
    for (int t = seg * 128; t < (seg + 1) * 128; t++)
        acc = fmaf(g_alpha[t * 64 + b],
                   __half2float(g_eh[((size_t)t * 64 + b) * HID + h]), acc);
    g_cpart[(seg * BATCH + b) * HID + h] = acc;
}

// ---------------- x = concat(embedding[cur], c) ----------------
__global__ void build_x(const int* __restrict__ cur, const float* __restrict__ emb) {
    const int b = blockIdx.x, tid = threadIdx.x;
    const int tok = cur[b];
    for (int k = tid; k < EMBED; k += 512)
        g_x[b * (EMBED + HID) + k] = emb[(size_t)tok * EMBED + k];
    for (int k = tid; k < HID; k += 512) {
        float s = 0.f;
        #pragma unroll
        for (int p = 0; p < 8; p++) s += g_cpart[(p * BATCH + b) * HID + k];
        g_x[b * (EMBED + HID) + EMBED + k] = s;
    }
}

// ---------------- GRU gates (reduces K-split partials; optional fp16 h1 out) ----------------
__global__ void gru_gates(const float* __restrict__ hprev,
                          const float* __restrict__ b_ih,
                          const float* __restrict__ b_hh,
                          float* __restrict__ out1, float* __restrict__ out2,
                          int write_h1) {
    const int idx = blockIdx.x * 256 + threadIdx.x;
    const int b = idx >> 10, q = idx & 1023;
    const int base = b * 3072 + q;
    float ir = b_ih[q], iz = b_ih[q + 1024], in_ = b_ih[q + 2048];
    float hr = b_hh[q], hz = b_hh[q + 1024], hn = b_hh[q + 2048];
    #pragma unroll
    for (int p = 0; p < KSPL; p++) {
        const float* gi = g_gi + p * (BATCH * 3 * HID);
        const float* gh = g_gh + p * (BATCH * 3 * HID);
        ir += gi[base];        hr += gh[base];
        iz += gi[base + 1024]; hz += gh[base + 1024];
        in_ += gi[base + 2048]; hn += gh[base + 2048];
    }
    float r = 1.f / (1.f + __expf(-(ir + hr)));
    float z = 1.f / (1.f + __expf(-(iz + hz)));
    float n = tanhf(in_ + r * hn);
    float h = (1.f - z) * n + z * hprev[idx];
    out1[idx] = h;
    if (out2) out2[idx] = h;
    if (write_h1) g_h1h[idx] = __float2half_rn(h);
}

// ---------------- launch (single stream; graph-capture safe) ----------------
extern "C" void kernel_launch(void* const* d_in, const int* in_sizes, int n_in,
                              void* d_out, int out_size) {
    const int*   cur    = (const int*)d_in[0];
    const float* state  = (const float*)d_in[1];
    const float* enc    = (const float*)d_in[2];
    const float* emb    = (const float*)d_in[3];
    const float* w_att1 = (const float*)d_in[4];
    const float* w_att2 = (const float*)d_in[5];
    const float* w_ih0  = (const float*)d_in[6];
    const float* w_hh0  = (const float*)d_in[7];
    const float* b_ih0  = (const float*)d_in[8];
    const float* b_hh0  = (const float*)d_in[9];
    const float* w_ih1  = (const float*)d_in[10];
    const float* w_hh1  = (const float*)d_in[11];
    const float* b_ih1  = (const float*)d_in[12];
    const float* b_hh1  = (const float*)d_in[13];
    const float* w_out  = (const float*)d_in[14];
    const float* b_out  = (const float*)d_in[15];

    float* out = (float*)d_out;
    float* st0 = out + (size_t)BATCH * VOCAB;
    float* st1 = st0 + BATCH * HID;

    float *p_x, *p_gi, *p_gh, *p_h0;
    cudaGetSymbolAddress((void**)&p_x,  g_x);
    cudaGetSymbolAddress((void**)&p_gi, g_gi);
    cudaGetSymbolAddress((void**)&p_gh, g_gh);
    cudaGetSymbolAddress((void**)&p_h0, g_h0);

    cudaFuncSetAttribute(attn_mma, cudaFuncAttributeMaxDynamicSharedMemorySize,
                         SMEM_TOTAL_ATT);
    cudaFuncSetAttribute(logits_mma, cudaFuncAttributeMaxDynamicSharedMemorySize,
                         SMEM_TOTAL_LOG);

    const float* dec = state + (size_t)BATCH * HID;

    // 1. prep: merged w1e transpose + dproj gemm (latency-bound, like-with-like)
    prep_w1e_dproj<<<1024 + 64, 256>>>(w_att1, w_att1 + (size_t)HID * HID, dec);
    // 2. enc -> fp16 (bandwidth-bound, alone)
    prep_enc<<<PREP_MAIN_BLOCKS, 256>>>(enc);
    reduce_dproj<<<BATCH * HID / 256, 256>>>();
    // 3. attention energies (+ wout->fp16 aux)
    attn_mma<<<dim3(NCHUNK, 512 + AUXY), 512, SMEM_TOTAL_ATT>>>(w_att2, w_out);
    // 4. softmax
    softmax_kernel<<<BATCH, 256>>>();
    // 5. context (fp16 enc)
    context_kernel<<<dim3(BATCH, 8), 1024>>>();
    // 6. x = concat(emb, c)
    build_x<<<BATCH, 512>>>(cur, emb);
    // 7. GRU layer 0: gi + gh in ONE launch
    gru_gemms<<<dim3(96, KSPL), 256>>>(p_x, w_ih0, p_gi, EMBED + HID,
                                       state, w_hh0, p_gh, HID);
    gru_gates<<<256, 256>>>(state, b_ih0, b_hh0, st0, p_h0, 0);
    // 8. GRU layer 1: gi + gh in ONE launch (writes fp16 h1)
    gru_gemms<<<dim3(96, KSPL), 256>>>(p_h0, w_ih1, p_gi, HID,
                                       dec, w_hh1, p_gh, HID);
    gru_gates<<<256, 256>>>(dec, b_ih1, b_hh1, st1, nullptr, 1);
    // 9. logits
    logits_mma<<<(VOCAB + 127) / 128, 256, SMEM_TOTAL_LOG>>>(b_out, out);
}

// round 17
// speedup vs baseline: 1.2935x; 1.0110x over previous
#include <cuda_runtime.h>
#include <cuda_fp16.h>
#include <cstdint>
#include <cstddef>

#define HID    1024
#define EMBED  512
#define BATCH  64
#define MAXLEN 1024
#define VOCAB  50257
#define NCHUNK 8
#define KSPL   4
#define PREP_MAIN_BLOCKS ((MAXLEN * BATCH * HID) / (256 * 4))

// ---------------- scratch (no allocations allowed) ----------------
__device__ float  g_dproj[BATCH * HID];
__device__ float  g_dp4[KSPL * BATCH * HID];
__device__ float  g_epart[NCHUNK * MAXLEN * BATCH];
__device__ float  g_alpha[MAXLEN * BATCH];
__device__ float  g_cpart[8 * BATCH * HID];
__device__ float  g_x[BATCH * (EMBED + HID)];
__device__ float  g_gi[KSPL * BATCH * 3 * HID];
__device__ float  g_gh[KSPL * BATCH * 3 * HID];
__device__ float  g_h0[BATCH * HID];
__device__ __half g_bh[HID * HID];                     // w1e^T fp16 [n][k]
__device__ __half g_eh[(size_t)MAXLEN * BATCH * HID];  // enc fp16
__device__ __half g_wh[(size_t)VOCAB * HID];           // w_out fp16 [n][k]
__device__ __half g_h1h[BATCH * HID];                  // h1 fp16

// ---------------- K-split fp32 GEMM body (M=64, 256 threads, KSPL=4) ----------------
template <bool BT>
__device__ __forceinline__ void gemm_body(const float* __restrict__ A,
                                          const float* __restrict__ B,
                                          float* __restrict__ C,
                                          int N, int K, int ldc, int nT, int ks) {
    __shared__ float As[64][16];
    __shared__ float Bs[16][64];
    const int Kseg = K / KSPL;
    A += ks * Kseg;                              // row stride stays K
    const float* Bp = BT ? (B + ks * Kseg) : (B + (size_t)ks * Kseg * N);
    C += (size_t)ks * 64 * ldc;
    const int tid = threadIdx.x;
    const int tx  = tid & 15, ty = tid >> 4;
    const int m4  = tid >> 2, kq = tid & 3;

    float acc[4][4] = {};
    for (int k0 = 0; k0 < Kseg; k0 += 16) {
        float4 avv = *(const float4*)(A + (size_t)m4 * K + k0 + kq * 4);
        *(float4*)&As[m4][kq * 4] = avv;
        if (BT) {
            int n = tid >> 2;
            int gn = nT + n;
            float4 bv = make_float4(0.f, 0.f, 0.f, 0.f);
            if (gn < N) bv = *(const float4*)(Bp + (size_t)gn * K + k0 + kq * 4);
            Bs[kq * 4 + 0][n] = bv.x;
            Bs[kq * 4 + 1][n] = bv.y;
            Bs[kq * 4 + 2][n] = bv.z;
            Bs[kq * 4 + 3][n] = bv.w;
        } else {
            #pragma unroll
            for (int e2 = 0; e2 < 4; e2++) {
                int lin = tid + e2 * 256;
                int kk = lin >> 6, n = lin & 63;
                int gn = nT + n;
                Bs[kk][n] = (gn < N) ? Bp[(size_t)(k0 + kk) * N + gn] : 0.f;
            }
        }
        __syncthreads();
        #pragma unroll
        for (int kk = 0; kk < 16; kk++) {
            float4 b4 = *(const float4*)&Bs[kk][tx * 4];
            float bj[4] = {b4.x, b4.y, b4.z, b4.w};
            #pragma unroll
            for (int i = 0; i < 4; i++) {
                float a = As[ty * 4 + i][kk];
                #pragma unroll
                for (int j = 0; j < 4; j++) acc[i][j] = fmaf(a, bj[j], acc[i][j]);
            }
        }
        __syncthreads();
    }
    #pragma unroll
    for (int i = 0; i < 4; i++) {
        int m = ty * 4 + i;
        #pragma unroll
        for (int j = 0; j < 4; j++) {
            int n = nT + tx * 4 + j;
            if (n < N) C[(size_t)m * ldc + n] = acc[i][j];
        }
    }
}

// ---------------- merged GRU projections: gi (blocks 0..47) + gh (48..95) ----------------
__global__ void gru_gemms(const float* __restrict__ A1, const float* __restrict__ B1,
                          float* __restrict__ C1, int K1,
                          const float* __restrict__ A2, const float* __restrict__ B2,
                          float* __restrict__ C2, int K2) {
    if (blockIdx.x < 48)
        gemm_body<true>(A1, B1, C1, 3 * HID, K1, 3 * HID, blockIdx.x * 64, blockIdx.y);
    else
        gemm_body<true>(A2, B2, C2, 3 * HID, K2, 3 * HID, (blockIdx.x - 48) * 64, blockIdx.y);
}

// ---------------- merged prep: w1e transpose (0..1023) + dproj gemm (1024..1087) ----------------
__global__ void prep_w1e_dproj(const float* __restrict__ w1e,
                               const float* __restrict__ w1d,
                               const float* __restrict__ dec) {
    const int bid = blockIdx.x;
    const int tid = threadIdx.x;
    if (bid < 1024) {
        __shared__ float tile[32][33];
        int k0 = (bid & 31) * 32, n0 = (bid >> 5) * 32;
        int tx = tid & 31, ty = tid >> 5;      // 32 x 8
        for (int i = ty; i < 32; i += 8)
            tile[i][tx] = w1e[(size_t)(k0 + i) * HID + n0 + tx];
        __syncthreads();
        for (int i = ty; i < 32; i += 8)
            g_bh[(size_t)(n0 + i) * HID + k0 + tx] = __float2half_rn(tile[tx][i]);
        return;
    }
    int g = bid - 1024;                        // 0..63
    gemm_body<false>(dec, w1d, g_dp4, HID, HID, HID, (g & 15) * 64, g >> 4);
}

// ---------------- prep: fp16 enc_states ----------------
__global__ void prep_enc(const float* __restrict__ enc) {
    size_t i = ((size_t)blockIdx.x * 256 + threadIdx.x) * 4;
    float4 v = *(const float4*)(enc + i);
    __half h[4];
    h[0] = __float2half_rn(v.x);
    h[1] = __float2half_rn(v.y);
    h[2] = __float2half_rn(v.z);
    h[3] = __float2half_rn(v.w);
    *(uint2*)(g_eh + i) = *(uint2*)h;
}

// ---------------- prep: fp16 w_out (standalone, bandwidth-bound) ----------------
__global__ void prep_wout(const float* __restrict__ w) {
    size_t i = ((size_t)blockIdx.x * 256 + threadIdx.x) * 4;
    if (i + 3 >= (size_t)VOCAB * HID) return;
    float4 v = *(const float4*)(w + i);
    __half h[4];
    h[0] = __float2half_rn(v.x);
    h[1] = __float2half_rn(v.y);
    h[2] = __float2half_rn(v.z);
    h[3] = __float2half_rn(v.w);
    *(uint2*)(g_wh + i) = *(uint2*)h;
}

// ---------------- reduce dproj partials ----------------
__global__ void reduce_dproj() {
    int i = blockIdx.x * 256 + threadIdx.x;
    float s = 0.f;
    #pragma unroll
    for (int p = 0; p < KSPL; p++) s += g_dp4[p * (BATCH * HID) + i];
    g_dproj[i] = s;
}

// ---------------- helpers ----------------
__device__ __forceinline__ uint32_t smem_u32(const void* p) {
    uint32_t a;
    asm("{ .reg .u64 t; cvta.to.shared.u64 t, %1; cvt.u32.u64 %0, t; }" : "=r"(a) : "l"(p));
    return a;
}
__device__ __forceinline__ void cp16(void* s, const void* g) {
    asm volatile("cp.async.cg.shared.global [%0], [%1], 16;"
                 :: "r"(smem_u32(s)), "l"(g));
}
__device__ __forceinline__ void cp_commit() {
    asm volatile("cp.async.commit_group;" ::: "memory");
}
template <int N>
__device__ __forceinline__ void cp_wait() {
    asm volatile("cp.async.wait_group %0;" :: "n"(N) : "memory");
}
__device__ __forceinline__ void mma16816(float* d, const uint32_t* a, const uint32_t* b) {
    asm volatile("mma.sync.aligned.m16n8k16.row.col.f32.f16.f16.f32 "
                 "{%0,%1,%2,%3}, {%4,%5,%6,%7}, {%8,%9}, {%0,%1,%2,%3};"
                 : "+f"(d[0]), "+f"(d[1]), "+f"(d[2]), "+f"(d[3])
                 : "r"(a[0]), "r"(a[1]), "r"(a[2]), "r"(a[3]),
                   "r"(b[0]), "r"(b[1]));
}
__device__ __forceinline__ void ldsm4(uint32_t* r, uint32_t addr) {
    asm volatile("ldmatrix.sync.aligned.m8n8.x4.shared.b16 {%0,%1,%2,%3}, [%4];"
                 : "=r"(r[0]), "=r"(r[1]), "=r"(r[2]), "=r"(r[3]) : "r"(addr));
}

// ================= attention GEMM (pure; no aux) =================
#define ASTRIDE 72
#define MATH (128 * ASTRIDE)
#define STAGE_BYTES (2 * MATH * 2)
#define NSTAGE 4
#define SMEM_TOTAL_ATT (NSTAGE * STAGE_BYTES)
#define KC 64
#define KT (HID / KC)

__global__ void __launch_bounds__(512, 1)
attn_mma(const float* __restrict__ w2) {
    extern __shared__ char smem[];
    const int tid = threadIdx.x;
    const uint32_t sbase = smem_u32(smem);
    const int bn = blockIdx.x;
    const int mt = blockIdx.y;
    const int wid = tid >> 5, lane = tid & 31;
    const int wm = wid >> 2, wn = wid & 3;
    const int qr = lane >> 2, qc = lane & 3;

    const __half* gAh = g_eh + (size_t)mt * 128 * HID;
    const __half* gBh = g_bh + (size_t)(bn * 128) * HID;

    const int lr = tid >> 2, lc = tid & 3;

    auto issue_load = [&](int kt) {
        char* base = smem + (kt % NSTAGE) * STAGE_BYTES;
        __half* sAh = (__half*)base;
        __half* sBh = sAh + MATH;
        #pragma unroll
        for (int i = 0; i < 2; i++) {
            int c = lc + i * 4;
            size_t go = (size_t)lr * HID + kt * KC + c * 8;
            int so = lr * ASTRIDE + c * 8;
            cp16(sAh + so, gAh + go);
            cp16(sBh + so, gBh + go);
        }
        cp_commit();
    };

    int offA[2];
    #pragma unroll
    for (int m = 0; m < 2; m++)
        offA[m] = ((wm * 32 + m * 16 + (lane & 15)) * ASTRIDE + (lane >> 4) * 8) * 2;
    int offB[2];
    #pragma unroll
    for (int j = 0; j < 2; j++)
        offB[j] = ((wn * 32 + (2 * j + (lane >> 4)) * 8 + (lane & 7)) * ASTRIDE
                   + ((lane >> 3) & 1) * 8) * 2;

    float acc[2][4][4] = {};

    auto compute = [&](int kt) {
        const uint32_t base = sbase + (kt % NSTAGE) * STAGE_BYTES;
        const uint32_t uAh = base;
        const uint32_t uBh = base + MATH * 2;
        #pragma unroll
        for (int ks = 0; ks < KC; ks += 16) {
            uint32_t ah[2][4], bh[4][2];
            #pragma unroll
            for (int m = 0; m < 2; m++)
                ldsm4(ah[m], uAh + offA[m] + ks * 2);
            #pragma unroll
            for (int j = 0; j < 2; j++) {
                uint32_t r[4];
                ldsm4(r, uBh + offB[j] + ks * 2);
                bh[2 * j][0] = r[0]; bh[2 * j][1] = r[1];
                bh[2 * j + 1][0] = r[2]; bh[2 * j + 1][1] = r[3];
            }
            #pragma unroll
            for (int m = 0; m < 2; m++)
                #pragma unroll
                for (int n = 0; n < 4; n++) mma16816(acc[m][n], ah[m], bh[n]);
        }
    };

    issue_load(0);
    issue_load(1);
    issue_load(2);
    for (int kt = 0; kt < KT; kt++) {
        cp_wait<2>();
        __syncthreads();
        if (kt + 3 < KT) issue_load(kt + 3);
        else cp_commit();
        compute(kt);
    }

    float rsum[2][2] = {};
    #pragma unroll
    for (int m = 0; m < 2; m++) {
        #pragma unroll
        for (int n = 0; n < 4; n++) {
            int ng0 = bn * 128 + wn * 32 + n * 8 + qc * 2;
            float w20 = w2[ng0], w21 = w2[ng0 + 1];
            #pragma unroll
            for (int pr = 0; pr < 2; pr++) {
                int row_local = wm * 32 + m * 16 + qr + pr * 8;
                int b = row_local & 63;
                const float* dp = g_dproj + (size_t)b * HID + ng0;
                rsum[m][pr] += tanhf(acc[m][n][pr * 2 + 0] + dp[0]) * w20
                             + tanhf(acc[m][n][pr * 2 + 1] + dp[1]) * w21;
            }
        }
    }
    #pragma unroll
    for (int m = 0; m < 2; m++)
        #pragma unroll
        for (int pr = 0; pr < 2; pr++) {
            float v = rsum[m][pr];
            v += __shfl_xor_sync(0xffffffffu, v, 1);
            v += __shfl_xor_sync(0xffffffffu, v, 2);
            rsum[m][pr] = v;
        }
    float* part = (float*)smem;
    __syncthreads();
    if (qc == 0) {
        #pragma unroll
        for (int m = 0; m < 2; m++)
            #pragma unroll
            for (int pr = 0; pr < 2; pr++)
                part[(wm * 32 + m * 16 + qr + pr * 8) * 4 + wn] = rsum[m][pr];
    }
    __syncthreads();
    if (tid < 128) {
        float e = part[tid * 4 + 0] + part[tid * 4 + 1] + part[tid * 4 + 2] + part[tid * 4 + 3];
        g_epart[(size_t)bn * (MAXLEN * BATCH) + mt * 128 + tid] = e;
    }
}

// ================= logits GEMM: single-pass fp16 =================
#define L_ASTR 72
#define L_MA (64 * L_ASTR)
#define L_MB (128 * L_ASTR)
#define L_STAGE ((L_MA + L_MB) * 2)
#define L_NSTAGE 4
#define SMEM_TOTAL_LOG (L_NSTAGE * L_STAGE)

__global__ void __launch_bounds__(256, 1)
logits_mma(const float* __restrict__ bias, float* __restrict__ out) {
    extern __shared__ char smem[];
    const uint32_t sbase = smem_u32(smem);
    const int n0 = blockIdx.x * 128;
    const int tid = threadIdx.x;
    const int wid = tid >> 5, lane = tid & 31;
    const int wm = wid >> 2, wn = wid & 3;
    const int qr = lane >> 2, qc = lane & 3;

    const int ar = tid >> 2, ac = tid & 3;
    const int br = tid >> 1, bc0 = (tid & 1) * 4;

    auto issue_load = [&](int kt) {
        char* base = smem + (kt % L_NSTAGE) * L_STAGE;
        __half* sAh = (__half*)base;
        __half* sB  = sAh + L_MA;
        #pragma unroll
        for (int i = 0; i < 2; i++) {
            int c = ac + i * 4;
            size_t go = (size_t)ar * HID + kt * KC + c * 8;
            cp16(sAh + ar * L_ASTR + c * 8, g_h1h + go);
        }
        int gn = n0 + br; if (gn >= VOCAB) gn = VOCAB - 1;
        #pragma unroll
        for (int i = 0; i < 4; i++) {
            int c = bc0 + i;
            cp16(sB + br * L_ASTR + c * 8, g_wh + (size_t)gn * HID + kt * KC + c * 8);
        }
        cp_commit();
    };

    int offA[2];
    #pragma unroll
    for (int m = 0; m < 2; m++)
        offA[m] = ((wm * 32 + m * 16 + (lane & 15)) * L_ASTR + (lane >> 4) * 8) * 2;
    int offB[2];
    #pragma unroll
    for (int j = 0; j < 2; j++)
        offB[j] = ((wn * 32 + (2 * j + (lane >> 4)) * 8 + (lane & 7)) * L_ASTR
                   + ((lane >> 3) & 1) * 8) * 2;

    float acc[2][4][4] = {};

    auto compute = [&](int kt) {
        const uint32_t base = sbase + (kt % L_NSTAGE) * L_STAGE;
        const uint32_t uAh = base;
        const uint32_t uB  = base + L_MA * 2;
        #pragma unroll
        for (int ks = 0; ks < KC; ks += 16) {
            uint32_t ah[2][4], bb[4][2];
            #pragma unroll
            for (int m = 0; m < 2; m++)
                ldsm4(ah[m], uAh + offA[m] + ks * 2);
            #pragma unroll
            for (int j = 0; j < 2; j++) {
                uint32_t r[4];
                ldsm4(r, uB + offB[j] + ks * 2);
                bb[2 * j][0] = r[0]; bb[2 * j][1] = r[1];
                bb[2 * j + 1][0] = r[2]; bb[2 * j + 1][1] = r[3];
            }
            #pragma unroll
            for (int m = 0; m < 2; m++)
                #pragma unroll
                for (int n = 0; n < 4; n++) mma16816(acc[m][n], ah[m], bb[n]);
        }
    };

    issue_load(0);
    issue_load(1);
    issue_load(2);
    for (int kt = 0; kt < KT; kt++) {
        cp_wait<2>();
        __syncthreads();
        if (kt + 3 < KT) issue_load(kt + 3);
        else cp_commit();
        compute(kt);
    }

    #pragma unroll
    for (int m = 0; m < 2; m++) {
        #pragma unroll
        for (int n = 0; n < 4; n++) {
            int col = n0 + wn * 32 + n * 8 + qc * 2;
            #pragma unroll
            for (int pr = 0; pr < 2; pr++) {
                int row = wm * 32 + m * 16 + qr + pr * 8;
                if (col < VOCAB)
                    out[(size_t)row * VOCAB + col] = acc[m][n][pr * 2 + 0] + bias[col];
                if (col + 1 < VOCAB)
                    out[(size_t)row * VOCAB + col + 1] = acc[m][n][pr * 2 + 1] + bias[col + 1];
            }
        }
    }
}

// ---------------- softmax over t ----------------
__global__ void softmax_kernel() {
    const int b = blockIdx.x;
    __shared__ float es[MAXLEN];
    __shared__ float red[256];
    const int tid = threadIdx.x;

    float mx = -1e30f;
    for (int t = tid; t < MAXLEN; t += 256) {
        float s = 0.f;
        #pragma unroll
        for (int p = 0; p < NCHUNK; p++) s += g_epart[p * (MAXLEN * BATCH) + t * 64 + b];
        es[t] = s;
        mx = fmaxf(mx, s);
    }
    red[tid] = mx; __syncthreads();
    for (int s2 = 128; s2; s2 >>= 1) {
        if (tid < s2) red[tid] = fmaxf(red[tid], red[tid + s2]);
        __syncthreads();
    }
    mx = red[0]; __syncthreads();

    float sum = 0.f;
    for (int t = tid; t < MAXLEN; t += 256) {
        float v = __expf(es[t] - mx);
        es[t] = v;
        sum += v;
    }
    red[tid] = sum; __syncthreads();
    for (int s2 = 128; s2; s2 >>= 1) {
        if (tid < s2) red[tid] += red[tid + s2];
        __syncthreads();
    }
    float inv = 1.f / red[0];
    for (int t = tid; t < MAXLEN; t += 256) g_alpha[t * 64 + b] = es[t] * inv;
}

// ---------------- context (fp16 enc) ----------------
__global__ void context_kernel() {
    const int b = blockIdx.x, seg = blockIdx.y;
    const int h = threadIdx.x;
    float acc = 0.f;
    #pragma unroll 4
    for (int t = seg * 128; t < (seg + 1) * 128; t++)
        acc = fmaf(g_alpha[t * 64 + b],
                   __half2float(g_eh[((size_t)t * 64 + b) * HID + h]), acc);
    g_cpart[(seg * BATCH + b) * HID + h] = acc;
}

// ---------------- x = concat(embedding[cur], c) ----------------
__global__ void build_x(const int* __restrict__ cur, const float* __restrict__ emb) {
    const int b = blockIdx.x, tid = threadIdx.x;
    const int tok = cur[b];
    for (int k = tid; k < EMBED; k += 512)
        g_x[b * (EMBED + HID) + k] = emb[(size_t)tok * EMBED + k];
    for (int k = tid; k < HID; k += 512) {
        float s = 0.f;
        #pragma unroll
        for (int p = 0; p < 8; p++) s += g_cpart[(p * BATCH + b) * HID + k];
        g_x[b * (EMBED + HID) + EMBED + k] = s;
    }
}

// ---------------- GRU gates (reduces K-split partials; optional fp16 h1 out) ----------------
__global__ void gru_gates(const float* __restrict__ hprev,
                          const float* __restrict__ b_ih,
                          const float* __restrict__ b_hh,
                          float* __restrict__ out1, float* __restrict__ out2,
                          int write_h1) {
    const int idx = blockIdx.x * 256 + threadIdx.x;
    const int b = idx >> 10, q = idx & 1023;
    const int base = b * 3072 + q;
    float ir = b_ih[q], iz = b_ih[q + 1024], in_ = b_ih[q + 2048];
    float hr = b_hh[q], hz = b_hh[q + 1024], hn = b_hh[q + 2048];
    #pragma unroll
    for (int p = 0; p < KSPL; p++) {
        const float* gi = g_gi + p * (BATCH * 3 * HID);
        const float* gh = g_gh + p * (BATCH * 3 * HID);
        ir += gi[base];        hr += gh[base];
        iz += gi[base + 1024]; hz += gh[base + 1024];
        in_ += gi[base + 2048]; hn += gh[base + 2048];
    }
    float r = 1.f / (1.f + __expf(-(ir + hr)));
    float z = 1.f / (1.f + __expf(-(iz + hz)));
    float n = tanhf(in_ + r * hn);
    float h = (1.f - z) * n + z * hprev[idx];
    out1[idx] = h;
    if (out2) out2[idx] = h;
    if (write_h1) g_h1h[idx] = __float2half_rn(h);
}

// ---------------- launch (single stream; graph-capture safe) ----------------
extern "C" void kernel_launch(void* const* d_in, const int* in_sizes, int n_in,
                              void* d_out, int out_size) {
    const int*   cur    = (const int*)d_in[0];
    const float* state  = (const float*)d_in[1];
    const float* enc    = (const float*)d_in[2];
    const float* emb    = (const float*)d_in[3];
    const float* w_att1 = (const float*)d_in[4];
    const float* w_att2 = (const float*)d_in[5];
    const float* w_ih0  = (const float*)d_in[6];
    const float* w_hh0  = (const float*)d_in[7];
    const float* b_ih0  = (const float*)d_in[8];
    const float* b_hh0  = (const float*)d_in[9];
    const float* w_ih1  = (const float*)d_in[10];
    const float* w_hh1  = (const float*)d_in[11];
    const float* b_ih1  = (const float*)d_in[12];
    const float* b_hh1  = (const float*)d_in[13];
    const float* w_out  = (const float*)d_in[14];
    const float* b_out  = (const float*)d_in[15];

    float* out = (float*)d_out;
    float* st0 = out + (size_t)BATCH * VOCAB;
    float* st1 = st0 + BATCH * HID;

    float *p_x, *p_gi, *p_gh, *p_h0;
    cudaGetSymbolAddress((void**)&p_x,  g_x);
    cudaGetSymbolAddress((void**)&p_gi, g_gi);
    cudaGetSymbolAddress((void**)&p_gh, g_gh);
    cudaGetSymbolAddress((void**)&p_h0, g_h0);

    cudaFuncSetAttribute(attn_mma, cudaFuncAttributeMaxDynamicSharedMemorySize,
                         SMEM_TOTAL_ATT);
    cudaFuncSetAttribute(logits_mma, cudaFuncAttributeMaxDynamicSharedMemorySize,
                         SMEM_TOTAL_LOG);

    const float* dec = state + (size_t)BATCH * HID;

    // 1. prep: merged w1e transpose + dproj gemm (latency-bound, like-with-like)
    prep_w1e_dproj<<<1024 + 64, 256>>>(w_att1, w_att1 + (size_t)HID * HID, dec);
    // 2. enc -> fp16 (bandwidth-bound, alone)
    prep_enc<<<PREP_MAIN_BLOCKS, 256>>>(enc);
    reduce_dproj<<<BATCH * HID / 256, 256>>>();
    // 3. attention energies (pure tensor kernel, no aux)
    attn_mma<<<dim3(NCHUNK, 512), 512, SMEM_TOTAL_ATT>>>(w_att2);
    // 4. w_out -> fp16 (standalone bandwidth kernel)
    prep_wout<<<((int)(((size_t)VOCAB * HID) / 4) + 255) / 256, 256>>>(w_out);
    // 5. softmax
    softmax_kernel<<<BATCH, 256>>>();
    // 6. context (fp16 enc)
    context_kernel<<<dim3(BATCH, 8), 1024>>>();
    // 7. x = concat(emb, c)
    build_x<<<BATCH, 512>>>(cur, emb);
    // 8. GRU layer 0: gi + gh in ONE launch
    gru_gemms<<<dim3(96, KSPL), 256>>>(p_x, w_ih0, p_gi, EMBED + HID,
                                       state, w_hh0, p_gh, HID);
    gru_gates<<<256, 256>>>(state, b_ih0, b_hh0, st0, p_h0, 0);
    // 9. GRU layer 1: gi + gh in ONE launch (writes fp16 h1)
    gru_gemms<<<dim3(96, KSPL), 256>>>(p_h0, w_ih1, p_gi, HID,
                                       dec, w_hh1, p_gh, HID);
    gru_gates<<<256, 256>>>(dec, b_ih1, b_hh1, st1, nullptr, 1);
    // 10. logits
    logits_mma<<<(VOCAB + 127) / 128, 256, SMEM_TOTAL_LOG>>>(b_out, out);
}